// round 1
// baseline (speedup 1.0000x reference)
#include <cuda_runtime.h>
#include <cuda_bf16.h>
#include <math.h>

// Problem constants
constexpr int Bb = 2;
constexpr int T  = 2048;
constexpr int C  = 1024;
constexpr int Hh = 16;
constexpr int Dd = 64;
constexpr int M  = Bb * T;       // 4096 tokens
constexpr int FF = 4 * C;        // 4096

// ---------------- scratch (static device memory; no allocation) -------------
__device__ float g_h  [M * C];       // layernorm output (reused for ln1/ln2)
__device__ float g_q  [M * C];       // head layout [B,H,T,D]
__device__ float g_k  [M * C];
__device__ float g_v  [M * C];
__device__ float g_y  [M * C];       // attention output, token layout [M,C]
__device__ float g_x1 [M * C];       // x + attn residual
__device__ float g_hid[(size_t)M * FF]; // MLP hidden

// ---------------- LayerNorm: one block per row ------------------------------
__global__ void ln_kernel(const float* __restrict__ X,
                          const float* __restrict__ w,
                          const float* __restrict__ b,
                          float* __restrict__ out)
{
    int row = blockIdx.x;
    int tid = threadIdx.x;                 // 256 threads, 4 elems each
    const float4 xv = *(const float4*)&X[(size_t)row * C + tid * 4];

    float s  = xv.x + xv.y + xv.z + xv.w;
    float sq = xv.x*xv.x + xv.y*xv.y + xv.z*xv.z + xv.w*xv.w;

    #pragma unroll
    for (int off = 16; off > 0; off >>= 1) {
        s  += __shfl_xor_sync(0xffffffffu, s,  off);
        sq += __shfl_xor_sync(0xffffffffu, sq, off);
    }
    __shared__ float ss[8], ssq[8];
    __shared__ float mu_s, rstd_s;
    int lane = tid & 31, wid = tid >> 5;
    if (lane == 0) { ss[wid] = s; ssq[wid] = sq; }
    __syncthreads();
    if (tid == 0) {
        float ts = 0.f, tq = 0.f;
        #pragma unroll
        for (int i = 0; i < 8; i++) { ts += ss[i]; tq += ssq[i]; }
        float mu  = ts * (1.0f / C);
        float var = tq * (1.0f / C) - mu * mu;
        mu_s   = mu;
        rstd_s = rsqrtf(var + 1e-5f);
    }
    __syncthreads();
    float mu = mu_s, r = rstd_s;

    const float4 wv = *(const float4*)&w[tid * 4];
    const float4 bv = *(const float4*)&b[tid * 4];
    float4 o;
    o.x = (xv.x - mu) * r * wv.x + bv.x;
    o.y = (xv.y - mu) * r * wv.y + bv.y;
    o.z = (xv.z - mu) * r * wv.z + bv.z;
    o.w = (xv.w - mu) * r * wv.w + bv.w;
    *(float4*)&out[(size_t)row * C + tid * 4] = o;
}

// ---------------- SGEMM 128x128x16, 8x8 per thread, fused epilogues ---------
// EPI: 0 = head-layout scatter (QKV), 1 = residual add, 2 = exact GELU
template<int EPI>
__global__ __launch_bounds__(256)
void gemm_kernel(const float* __restrict__ A,     // [M,K] row-major
                 const float* __restrict__ W,     // [K,N] row-major
                 const float* __restrict__ bias,  // [N]
                 const float* __restrict__ resid, // [M,N] (EPI==1)
                 float* __restrict__ out,
                 int Mm, int Nn, int Kk)
{
    __shared__ float As[16][132];  // [k][m], padded, 16B-aligned rows
    __shared__ float Bs[16][132];  // [k][n]

    int tid = threadIdx.x;
    int bm  = blockIdx.y * 128;
    int bn  = blockIdx.x * 128;
    int tx  = tid & 15;            // 16 thread-cols
    int ty  = tid >> 4;            // 16 thread-rows

    float acc[8][8] = {};

    for (int k0 = 0; k0 < Kk; k0 += 16) {
        // A tile: 128 rows x 16 cols = 512 float4, 2 per thread; transpose into As
        #pragma unroll
        for (int i = 0; i < 2; i++) {
            int idx  = tid * 2 + i;        // 0..511
            int row  = idx >> 2;           // 4 float4 per row
            int col4 = idx & 3;
            float4 a = *(const float4*)&A[(size_t)(bm + row) * Kk + k0 + col4 * 4];
            As[col4 * 4 + 0][row] = a.x;
            As[col4 * 4 + 1][row] = a.y;
            As[col4 * 4 + 2][row] = a.z;
            As[col4 * 4 + 3][row] = a.w;
        }
        // B tile: 16 rows x 128 cols = 512 float4
        #pragma unroll
        for (int i = 0; i < 2; i++) {
            int idx  = tid * 2 + i;
            int row  = idx >> 5;           // 32 float4 per row
            int col4 = idx & 31;
            float4 b = *(const float4*)&W[(size_t)(k0 + row) * Nn + bn + col4 * 4];
            *(float4*)&Bs[row][col4 * 4] = b;
        }
        __syncthreads();

        #pragma unroll
        for (int kk = 0; kk < 16; kk++) {
            float4 a0 = *(const float4*)&As[kk][ty * 8];
            float4 a1 = *(const float4*)&As[kk][ty * 8 + 4];
            float4 b0 = *(const float4*)&Bs[kk][tx * 8];
            float4 b1 = *(const float4*)&Bs[kk][tx * 8 + 4];
            float af[8] = {a0.x,a0.y,a0.z,a0.w,a1.x,a1.y,a1.z,a1.w};
            float bf[8] = {b0.x,b0.y,b0.z,b0.w,b1.x,b1.y,b1.z,b1.w};
            #pragma unroll
            for (int i = 0; i < 8; i++)
                #pragma unroll
                for (int j = 0; j < 8; j++)
                    acc[i][j] += af[i] * bf[j];
        }
        __syncthreads();
    }

    // epilogue
    #pragma unroll
    for (int i = 0; i < 8; i++) {
        int r = bm + ty * 8 + i;
        #pragma unroll
        for (int j = 0; j < 8; j++) {
            int c = bn + tx * 8 + j;
            float v = acc[i][j] + bias[c];
            if (EPI == 2) {
                v = 0.5f * v * (1.0f + erff(v * 0.70710678118654752f));
            }
            if (EPI == 1) {
                v += resid[(size_t)r * Nn + c];
            }
            if (EPI == 0) {
                // token r = b*T + t, col c = h*64 + d  ->  [B,H,T,D]
                int bi = r >> 11, t = r & 2047;
                int hi = c >> 6,  d = c & 63;
                out[(((size_t)(bi * Hh + hi)) * T + t) * Dd + d] = v;
            } else {
                out[(size_t)r * Nn + c] = v;
            }
        }
    }
}

// ---------------- Flash attention (causal), fp32 ----------------------------
// grid: (T/64, B*H); block: 64 threads, 1 q-row per thread
__global__ __launch_bounds__(64)
void attn_kernel(const float* __restrict__ Q,
                 const float* __restrict__ K,
                 const float* __restrict__ V,
                 float* __restrict__ Y)
{
    __shared__ float Ks[64][68];
    __shared__ float Vs[64][68];

    int bh  = blockIdx.y;
    int qb  = blockIdx.x;
    int tid = threadIdx.x;
    int qrow = qb * 64 + tid;

    const float* Qp = Q + (size_t)bh * T * Dd;
    const float* Kp = K + (size_t)bh * T * Dd;
    const float* Vp = V + (size_t)bh * T * Dd;

    float qreg[64];
    #pragma unroll
    for (int d4 = 0; d4 < 16; d4++) {
        float4 qv = *(const float4*)&Qp[(size_t)qrow * Dd + d4 * 4];
        qreg[d4*4+0] = qv.x; qreg[d4*4+1] = qv.y;
        qreg[d4*4+2] = qv.z; qreg[d4*4+3] = qv.w;
    }

    float m = -1e30f, l = 0.0f;
    float o[64];
    #pragma unroll
    for (int d = 0; d < 64; d++) o[d] = 0.0f;

    for (int kt = 0; kt <= qb; kt++) {
        // cooperative coalesced load of K/V 64x64 tiles
        #pragma unroll
        for (int rr = 0; rr < 16; rr++) {
            int idx = rr * 64 + tid;       // 0..1023 float4s
            int row = idx >> 4;
            int c4  = idx & 15;
            *(float4*)&Ks[row][c4*4] =
                *(const float4*)&Kp[((size_t)(kt*64 + row)) * Dd + c4 * 4];
            *(float4*)&Vs[row][c4*4] =
                *(const float4*)&Vp[((size_t)(kt*64 + row)) * Dd + c4 * 4];
        }
        __syncthreads();

        float s[64];
        #pragma unroll 4
        for (int j = 0; j < 64; j++) {
            float sum = 0.0f;
            #pragma unroll
            for (int d4 = 0; d4 < 16; d4++) {
                float4 k4 = *(const float4*)&Ks[j][d4*4];
                sum += qreg[d4*4+0]*k4.x + qreg[d4*4+1]*k4.y
                     + qreg[d4*4+2]*k4.z + qreg[d4*4+3]*k4.w;
            }
            s[j] = sum * 0.125f;           // 1/sqrt(64)
        }

        if (kt == qb) {                    // diagonal tile: causal mask
            #pragma unroll
            for (int j = 0; j < 64; j++)
                if (kt * 64 + j > qrow) s[j] = -1e30f;
        }

        float rowmax = m;
        #pragma unroll
        for (int j = 0; j < 64; j++) rowmax = fmaxf(rowmax, s[j]);
        float corr = __expf(m - rowmax);
        m = rowmax;
        l *= corr;
        #pragma unroll
        for (int d = 0; d < 64; d++) o[d] *= corr;

        #pragma unroll 4
        for (int j = 0; j < 64; j++) {
            float p = __expf(s[j] - m);
            l += p;
            #pragma unroll
            for (int d4 = 0; d4 < 16; d4++) {
                float4 v4 = *(const float4*)&Vs[j][d4*4];
                o[d4*4+0] += p * v4.x;
                o[d4*4+1] += p * v4.y;
                o[d4*4+2] += p * v4.z;
                o[d4*4+3] += p * v4.w;
            }
        }
        __syncthreads();
    }

    // write back to token layout [M, C]
    float inv = 1.0f / l;
    int bi = bh >> 4, hi = bh & 15;
    float* yp = Y + ((size_t)(bi * T + qrow)) * C + hi * Dd;
    #pragma unroll
    for (int d4 = 0; d4 < 16; d4++) {
        float4 ov;
        ov.x = o[d4*4+0] * inv;
        ov.y = o[d4*4+1] * inv;
        ov.z = o[d4*4+2] * inv;
        ov.w = o[d4*4+3] * inv;
        *(float4*)&yp[d4*4] = ov;
    }
}

// ---------------- launcher --------------------------------------------------
extern "C" void kernel_launch(void* const* d_in, const int* in_sizes, int n_in,
                              void* d_out, int out_size)
{
    const float* x     = (const float*)d_in[0];
    const float* ln1_w = (const float*)d_in[1];
    const float* ln1_b = (const float*)d_in[2];
    const float* wq    = (const float*)d_in[3];
    const float* bq    = (const float*)d_in[4];
    const float* wk    = (const float*)d_in[5];
    const float* bk    = (const float*)d_in[6];
    const float* wv    = (const float*)d_in[7];
    const float* bv    = (const float*)d_in[8];
    const float* wo    = (const float*)d_in[9];
    const float* bo    = (const float*)d_in[10];
    const float* ln2_w = (const float*)d_in[11];
    const float* ln2_b = (const float*)d_in[12];
    const float* w1    = (const float*)d_in[13];
    const float* b1    = (const float*)d_in[14];
    const float* w2    = (const float*)d_in[15];
    const float* b2    = (const float*)d_in[16];

    float *h, *q, *k, *v, *y, *x1, *hid;
    cudaGetSymbolAddress((void**)&h,   g_h);
    cudaGetSymbolAddress((void**)&q,   g_q);
    cudaGetSymbolAddress((void**)&k,   g_k);
    cudaGetSymbolAddress((void**)&v,   g_v);
    cudaGetSymbolAddress((void**)&y,   g_y);
    cudaGetSymbolAddress((void**)&x1,  g_x1);
    cudaGetSymbolAddress((void**)&hid, g_hid);

    float* out = (float*)d_out;

    // 1) LN1
    ln_kernel<<<M, 256>>>(x, ln1_w, ln1_b, h);
    // 2) Q,K,V projections (write head layout)
    gemm_kernel<0><<<dim3(C/128, M/128), 256>>>(h, wq, bq, nullptr, q, M, C, C);
    gemm_kernel<0><<<dim3(C/128, M/128), 256>>>(h, wk, bk, nullptr, k, M, C, C);
    gemm_kernel<0><<<dim3(C/128, M/128), 256>>>(h, wv, bv, nullptr, v, M, C, C);
    // 3) causal flash attention
    attn_kernel<<<dim3(T/64, Bb*Hh), 64>>>(q, k, v, y);
    // 4) output projection + residual
    gemm_kernel<1><<<dim3(C/128, M/128), 256>>>(y, wo, bo, x, x1, M, C, C);
    // 5) LN2
    ln_kernel<<<M, 256>>>(x1, ln2_w, ln2_b, h);
    // 6) MLP up + exact GELU
    gemm_kernel<2><<<dim3(FF/128, M/128), 256>>>(h, w1, b1, nullptr, hid, M, FF, C);
    // 7) MLP down + residual -> final output
    gemm_kernel<1><<<dim3(C/128, M/128), 256>>>(hid, w2, b2, x1, out, M, C, FF);
}

// round 3
// speedup vs baseline: 2.0383x; 2.0383x over previous
#include <cuda_runtime.h>
#include <math.h>
#include <cstdint>

// Problem constants
constexpr int Bb = 2;
constexpr int T  = 2048;
constexpr int C  = 1024;
constexpr int Hh = 16;
constexpr int Dd = 64;
constexpr int M  = Bb * T;       // 4096 tokens
constexpr int FF = 4 * C;        // 4096

// ---------------- scratch (static device memory; no allocation) -------------
__device__ float g_h  [M * C];       // LN output (tf32-rounded)
__device__ float g_q  [M * C];       // head layout [B,H,T,D]
__device__ float g_k  [M * C];
__device__ float g_v  [M * C];
__device__ float g_y  [M * C];       // attn out (tf32-rounded)
__device__ float g_x1 [M * C];
__device__ float g_hid[(size_t)M * FF]; // MLP hidden (tf32-rounded)
// transposed weights, [N][K] layout, tf32-rounded
__device__ float g_wtq[C * C];
__device__ float g_wtk[C * C];
__device__ float g_wtv[C * C];
__device__ float g_wto[C * C];
__device__ float g_wt1[(size_t)C * FF];
__device__ float g_wt2[(size_t)C * FF];

// ---------------- helpers ----------------------------------------------------
__device__ __forceinline__ uint32_t smem_u32(const void* p) {
    uint32_t a;
    asm("{ .reg .u64 t; cvta.to.shared.u64 t, %1; cvt.u32.u64 %0, t; }"
        : "=r"(a) : "l"(p));
    return a;
}
__device__ __forceinline__ float to_tf32(float x) {
    float r;
    asm("cvt.rna.tf32.f32 %0, %1;" : "=f"(r) : "f"(x));
    return r;
}
__device__ __forceinline__ void cp_async16(uint32_t dst, const void* src) {
    asm volatile("cp.async.cg.shared.global [%0], [%1], 16;"
                 :: "r"(dst), "l"(src) : "memory");
}
#define CP_COMMIT() asm volatile("cp.async.commit_group;" ::: "memory")
#define CP_WAIT(n)  asm volatile("cp.async.wait_group %0;" :: "n"(n) : "memory")

__device__ __forceinline__ void mma_tf32(float* c, const uint32_t* a, const uint32_t* b) {
    asm volatile(
        "mma.sync.aligned.m16n8k8.row.col.f32.tf32.tf32.f32 "
        "{%0,%1,%2,%3}, {%4,%5,%6,%7}, {%8,%9}, {%0,%1,%2,%3};"
        : "+f"(c[0]), "+f"(c[1]), "+f"(c[2]), "+f"(c[3])
        : "r"(a[0]), "r"(a[1]), "r"(a[2]), "r"(a[3]), "r"(b[0]), "r"(b[1]));
}

// ---------------- tf32 mma.sync GEMM, 128x128x32, fused epilogues ------------
// EPI: 0 = head-layout scatter (QKV), 1 = residual add, 2 = exact GELU (+tf32 round)
constexpr int LDK = 36;                        // padded row stride (floats)
constexpr int TILE_F = 128 * LDK;              // floats per tile buffer
constexpr int SMEM_SZ = 4 * TILE_F * 4;        // A0,B0,A1,B1 bytes = 73728

template<int EPI>
__global__ __launch_bounds__(256)
void gemm_mma(const float* __restrict__ A,     // [M,K] row-major, tf32 values
              const float* __restrict__ Bt,    // [N,K] row-major, tf32 values
              const float* __restrict__ bias,  // [N]
              const float* __restrict__ resid, // [M,N] (EPI==1)
              float* __restrict__ out,
              int Nn, int Kk)
{
    extern __shared__ float sm[];
    const uint32_t sbase = smem_u32(sm);
    const int tid  = threadIdx.x;
    const int wid  = tid >> 5;
    const int lane = tid & 31;
    const int qr   = lane >> 2;     // group id
    const int qc   = lane & 3;      // thread-in-group
    const int bm = blockIdx.y * 128;
    const int bn = blockIdx.x * 128;
    const int warp_m = (wid & 1) * 64;
    const int warp_n = (wid >> 1) * 32;
    const int KT = Kk >> 5;

    // tile buffer float offsets: A0, B0, A1, B1
    const int aoff[2] = { 0, 2 * TILE_F };
    const int boff[2] = { TILE_F, 3 * TILE_F };

    // this thread's 4 cp.async slots per tile (1024 float4 over 256 threads)
    // idx = i*256+tid ; row = idx>>3 ; c4 = idx&7
    auto issue_load = [&](int buf, int k0) {
        #pragma unroll
        for (int i = 0; i < 4; i++) {
            int idx = i * 256 + tid;
            int r = idx >> 3, c4 = idx & 7;
            cp_async16(sbase + (uint32_t)(aoff[buf] + r * LDK + c4 * 4) * 4,
                       &A[(size_t)(bm + r) * Kk + k0 + c4 * 4]);
        }
        #pragma unroll
        for (int i = 0; i < 4; i++) {
            int idx = i * 256 + tid;
            int r = idx >> 3, c4 = idx & 7;
            cp_async16(sbase + (uint32_t)(boff[buf] + r * LDK + c4 * 4) * 4,
                       &Bt[(size_t)(bn + r) * Kk + k0 + c4 * 4]);
        }
        CP_COMMIT();
    };

    float acc[4][4][4] = {};

    issue_load(0, 0);

    for (int kt = 0; kt < KT; kt++) {
        const int cur = kt & 1;
        if (kt + 1 < KT) issue_load(1 - cur, (kt + 1) * 32);
        if (kt + 1 < KT) { CP_WAIT(1); } else { CP_WAIT(0); }
        __syncthreads();

        const float* Asb = sm + aoff[cur];
        const float* Bsb = sm + boff[cur];

        #pragma unroll
        for (int ks = 0; ks < 4; ks++) {
            const int k0 = ks * 8;
            uint32_t a[4][4], b[4][2];
            #pragma unroll
            for (int im = 0; im < 4; im++) {
                const float* ap = &Asb[(warp_m + im * 16 + qr) * LDK + k0 + qc];
                a[im][0] = __float_as_uint(ap[0]);
                a[im][1] = __float_as_uint(ap[8 * LDK]);
                a[im][2] = __float_as_uint(ap[4]);
                a[im][3] = __float_as_uint(ap[8 * LDK + 4]);
            }
            #pragma unroll
            for (int jn = 0; jn < 4; jn++) {
                const float* bp = &Bsb[(warp_n + jn * 8 + qr) * LDK + k0 + qc];
                b[jn][0] = __float_as_uint(bp[0]);
                b[jn][1] = __float_as_uint(bp[4]);
            }
            #pragma unroll
            for (int im = 0; im < 4; im++)
                #pragma unroll
                for (int jn = 0; jn < 4; jn++)
                    mma_tf32(acc[im][jn], a[im], b[jn]);
        }
        __syncthreads();
    }

    // epilogue
    #pragma unroll
    for (int im = 0; im < 4; im++) {
        const int r0 = bm + warp_m + im * 16 + qr;
        const int r1 = r0 + 8;
        #pragma unroll
        for (int jn = 0; jn < 4; jn++) {
            const int c0 = bn + warp_n + jn * 8 + qc * 2;
            const float2 bv = *(const float2*)&bias[c0];
            float2 v0, v1;
            v0.x = acc[im][jn][0] + bv.x;
            v0.y = acc[im][jn][1] + bv.y;
            v1.x = acc[im][jn][2] + bv.x;
            v1.y = acc[im][jn][3] + bv.y;
            if (EPI == 2) {
                v0.x = 0.5f * v0.x * (1.0f + erff(v0.x * 0.70710678118654752f));
                v0.y = 0.5f * v0.y * (1.0f + erff(v0.y * 0.70710678118654752f));
                v1.x = 0.5f * v1.x * (1.0f + erff(v1.x * 0.70710678118654752f));
                v1.y = 0.5f * v1.y * (1.0f + erff(v1.y * 0.70710678118654752f));
                v0.x = to_tf32(v0.x); v0.y = to_tf32(v0.y);   // feeds next GEMM
                v1.x = to_tf32(v1.x); v1.y = to_tf32(v1.y);
            }
            if (EPI == 1) {
                const float2 q0 = *(const float2*)&resid[(size_t)r0 * Nn + c0];
                const float2 q1 = *(const float2*)&resid[(size_t)r1 * Nn + c0];
                v0.x += q0.x; v0.y += q0.y;
                v1.x += q1.x; v1.y += q1.y;
            }
            if (EPI == 0) {
                const int hi = c0 >> 6, dd = c0 & 63;
                {
                    const int bi = r0 >> 11, t = r0 & 2047;
                    *(float2*)&out[(((size_t)(bi * Hh + hi)) * T + t) * Dd + dd] = v0;
                }
                {
                    const int bi = r1 >> 11, t = r1 & 2047;
                    *(float2*)&out[(((size_t)(bi * Hh + hi)) * T + t) * Dd + dd] = v1;
                }
            } else {
                *(float2*)&out[(size_t)r0 * Nn + c0] = v0;
                *(float2*)&out[(size_t)r1 * Nn + c0] = v1;
            }
        }
    }
}

// ---------------- weight transpose [R,Cc] -> [Cc,R], tf32 rounding ----------
__global__ void transpose_kernel(const float* __restrict__ in, float* __restrict__ out,
                                 int R, int Cc)
{
    __shared__ float tile[32][33];
    int x = blockIdx.x * 32 + threadIdx.x;
    int y = blockIdx.y * 32 + threadIdx.y;
    #pragma unroll
    for (int j = 0; j < 32; j += 8)
        tile[threadIdx.y + j][threadIdx.x] = to_tf32(in[(size_t)(y + j) * Cc + x]);
    __syncthreads();
    int xo = blockIdx.y * 32 + threadIdx.x;
    int yo = blockIdx.x * 32 + threadIdx.y;
    #pragma unroll
    for (int j = 0; j < 32; j += 8)
        out[(size_t)(yo + j) * R + xo] = tile[threadIdx.x][threadIdx.y + j];
}

// ---------------- LayerNorm (tf32-rounded output) ----------------------------
__global__ void ln_kernel(const float* __restrict__ X,
                          const float* __restrict__ w,
                          const float* __restrict__ b,
                          float* __restrict__ out)
{
    int row = blockIdx.x;
    int tid = threadIdx.x;
    const float4 xv = *(const float4*)&X[(size_t)row * C + tid * 4];

    float s  = xv.x + xv.y + xv.z + xv.w;
    float sq = xv.x*xv.x + xv.y*xv.y + xv.z*xv.z + xv.w*xv.w;
    #pragma unroll
    for (int off = 16; off > 0; off >>= 1) {
        s  += __shfl_xor_sync(0xffffffffu, s,  off);
        sq += __shfl_xor_sync(0xffffffffu, sq, off);
    }
    __shared__ float ss[8], ssq[8];
    __shared__ float mu_s, rstd_s;
    int lane = tid & 31, wid = tid >> 5;
    if (lane == 0) { ss[wid] = s; ssq[wid] = sq; }
    __syncthreads();
    if (tid == 0) {
        float ts = 0.f, tq = 0.f;
        #pragma unroll
        for (int i = 0; i < 8; i++) { ts += ss[i]; tq += ssq[i]; }
        float mu  = ts * (1.0f / C);
        float var = tq * (1.0f / C) - mu * mu;
        mu_s = mu; rstd_s = rsqrtf(var + 1e-5f);
    }
    __syncthreads();
    float mu = mu_s, r = rstd_s;
    const float4 wv = *(const float4*)&w[tid * 4];
    const float4 bv = *(const float4*)&b[tid * 4];
    float4 o;
    o.x = to_tf32((xv.x - mu) * r * wv.x + bv.x);
    o.y = to_tf32((xv.y - mu) * r * wv.y + bv.y);
    o.z = to_tf32((xv.z - mu) * r * wv.z + bv.z);
    o.w = to_tf32((xv.w - mu) * r * wv.w + bv.w);
    *(float4*)&out[(size_t)row * C + tid * 4] = o;
}

// ---------------- Flash attention (causal), fp32 -----------------------------
__global__ __launch_bounds__(64)
void attn_kernel(const float* __restrict__ Q,
                 const float* __restrict__ K,
                 const float* __restrict__ V,
                 float* __restrict__ Y)
{
    __shared__ float Ks[64][68];
    __shared__ float Vs[64][68];

    int bh  = blockIdx.y;
    int qb  = blockIdx.x;
    int tid = threadIdx.x;
    int qrow = qb * 64 + tid;

    const float* Qp = Q + (size_t)bh * T * Dd;
    const float* Kp = K + (size_t)bh * T * Dd;
    const float* Vp = V + (size_t)bh * T * Dd;

    float qreg[64];
    #pragma unroll
    for (int d4 = 0; d4 < 16; d4++) {
        float4 qv = *(const float4*)&Qp[(size_t)qrow * Dd + d4 * 4];
        qreg[d4*4+0] = qv.x; qreg[d4*4+1] = qv.y;
        qreg[d4*4+2] = qv.z; qreg[d4*4+3] = qv.w;
    }

    float m = -1e30f, l = 0.0f;
    float o[64];
    #pragma unroll
    for (int d = 0; d < 64; d++) o[d] = 0.0f;

    for (int kt = 0; kt <= qb; kt++) {
        #pragma unroll
        for (int rr = 0; rr < 16; rr++) {
            int idx = rr * 64 + tid;
            int row = idx >> 4;
            int c4  = idx & 15;
            *(float4*)&Ks[row][c4*4] =
                *(const float4*)&Kp[((size_t)(kt*64 + row)) * Dd + c4 * 4];
            *(float4*)&Vs[row][c4*4] =
                *(const float4*)&Vp[((size_t)(kt*64 + row)) * Dd + c4 * 4];
        }
        __syncthreads();

        float s[64];
        #pragma unroll 4
        for (int j = 0; j < 64; j++) {
            float sum = 0.0f;
            #pragma unroll
            for (int d4 = 0; d4 < 16; d4++) {
                float4 k4 = *(const float4*)&Ks[j][d4*4];
                sum += qreg[d4*4+0]*k4.x + qreg[d4*4+1]*k4.y
                     + qreg[d4*4+2]*k4.z + qreg[d4*4+3]*k4.w;
            }
            s[j] = sum * 0.125f;
        }

        if (kt == qb) {
            #pragma unroll
            for (int j = 0; j < 64; j++)
                if (kt * 64 + j > qrow) s[j] = -1e30f;
        }

        float rowmax = m;
        #pragma unroll
        for (int j = 0; j < 64; j++) rowmax = fmaxf(rowmax, s[j]);
        float corr = __expf(m - rowmax);
        m = rowmax;
        l *= corr;
        #pragma unroll
        for (int d = 0; d < 64; d++) o[d] *= corr;

        #pragma unroll 4
        for (int j = 0; j < 64; j++) {
            float p = __expf(s[j] - m);
            l += p;
            #pragma unroll
            for (int d4 = 0; d4 < 16; d4++) {
                float4 v4 = *(const float4*)&Vs[j][d4*4];
                o[d4*4+0] += p * v4.x;
                o[d4*4+1] += p * v4.y;
                o[d4*4+2] += p * v4.z;
                o[d4*4+3] += p * v4.w;
            }
        }
        __syncthreads();
    }

    float inv = 1.0f / l;
    int bi = bh >> 4, hi = bh & 15;
    float* yp = Y + ((size_t)(bi * T + qrow)) * C + hi * Dd;
    #pragma unroll
    for (int d4 = 0; d4 < 16; d4++) {
        float4 ov;
        ov.x = to_tf32(o[d4*4+0] * inv);     // y feeds Wo GEMM
        ov.y = to_tf32(o[d4*4+1] * inv);
        ov.z = to_tf32(o[d4*4+2] * inv);
        ov.w = to_tf32(o[d4*4+3] * inv);
        *(float4*)&yp[d4*4] = ov;
    }
}

// ---------------- launcher ----------------------------------------------------
extern "C" void kernel_launch(void* const* d_in, const int* in_sizes, int n_in,
                              void* d_out, int out_size)
{
    const float* x     = (const float*)d_in[0];
    const float* ln1_w = (const float*)d_in[1];
    const float* ln1_b = (const float*)d_in[2];
    const float* wq    = (const float*)d_in[3];
    const float* bq    = (const float*)d_in[4];
    const float* wk    = (const float*)d_in[5];
    const float* bk    = (const float*)d_in[6];
    const float* wv    = (const float*)d_in[7];
    const float* bv    = (const float*)d_in[8];
    const float* wo    = (const float*)d_in[9];
    const float* bo    = (const float*)d_in[10];
    const float* ln2_w = (const float*)d_in[11];
    const float* ln2_b = (const float*)d_in[12];
    const float* w1    = (const float*)d_in[13];
    const float* b1    = (const float*)d_in[14];
    const float* w2    = (const float*)d_in[15];
    const float* b2    = (const float*)d_in[16];

    float *h, *q, *k, *v, *y, *x1, *hid;
    float *wtq, *wtk, *wtv, *wto, *wt1, *wt2;
    cudaGetSymbolAddress((void**)&h,   g_h);
    cudaGetSymbolAddress((void**)&q,   g_q);
    cudaGetSymbolAddress((void**)&k,   g_k);
    cudaGetSymbolAddress((void**)&v,   g_v);
    cudaGetSymbolAddress((void**)&y,   g_y);
    cudaGetSymbolAddress((void**)&x1,  g_x1);
    cudaGetSymbolAddress((void**)&hid, g_hid);
    cudaGetSymbolAddress((void**)&wtq, g_wtq);
    cudaGetSymbolAddress((void**)&wtk, g_wtk);
    cudaGetSymbolAddress((void**)&wtv, g_wtv);
    cudaGetSymbolAddress((void**)&wto, g_wto);
    cudaGetSymbolAddress((void**)&wt1, g_wt1);
    cudaGetSymbolAddress((void**)&wt2, g_wt2);

    float* out = (float*)d_out;

    cudaFuncSetAttribute(gemm_mma<0>, cudaFuncAttributeMaxDynamicSharedMemorySize, SMEM_SZ);
    cudaFuncSetAttribute(gemm_mma<1>, cudaFuncAttributeMaxDynamicSharedMemorySize, SMEM_SZ);
    cudaFuncSetAttribute(gemm_mma<2>, cudaFuncAttributeMaxDynamicSharedMemorySize, SMEM_SZ);

    dim3 tb(32, 8);
    // 0) transpose weights to [N][K], tf32-rounded
    transpose_kernel<<<dim3(C/32,  C/32),  tb>>>(wq, wtq, C,  C);
    transpose_kernel<<<dim3(C/32,  C/32),  tb>>>(wk, wtk, C,  C);
    transpose_kernel<<<dim3(C/32,  C/32),  tb>>>(wv, wtv, C,  C);
    transpose_kernel<<<dim3(C/32,  C/32),  tb>>>(wo, wto, C,  C);
    transpose_kernel<<<dim3(FF/32, C/32),  tb>>>(w1, wt1, C,  FF);
    transpose_kernel<<<dim3(C/32,  FF/32), tb>>>(w2, wt2, FF, C);

    // 1) LN1
    ln_kernel<<<M, 256>>>(x, ln1_w, ln1_b, h);
    // 2) Q,K,V projections (tf32 HMMA, scatter to head layout)
    gemm_mma<0><<<dim3(C/128,  M/128), 256, SMEM_SZ>>>(h, wtq, bq, nullptr, q, C, C);
    gemm_mma<0><<<dim3(C/128,  M/128), 256, SMEM_SZ>>>(h, wtk, bk, nullptr, k, C, C);
    gemm_mma<0><<<dim3(C/128,  M/128), 256, SMEM_SZ>>>(h, wtv, bv, nullptr, v, C, C);
    // 3) causal flash attention
    attn_kernel<<<dim3(T/64, Bb*Hh), 64>>>(q, k, v, y);
    // 4) output projection + residual
    gemm_mma<1><<<dim3(C/128,  M/128), 256, SMEM_SZ>>>(y, wto, bo, x, x1, C, C);
    // 5) LN2
    ln_kernel<<<M, 256>>>(x1, ln2_w, ln2_b, h);
    // 6) MLP up + exact GELU
    gemm_mma<2><<<dim3(FF/128, M/128), 256, SMEM_SZ>>>(h, wt1, b1, nullptr, hid, FF, C);
    // 7) MLP down + residual -> final output
    gemm_mma<1><<<dim3(C/128,  M/128), 256, SMEM_SZ>>>(hid, wt2, b2, x1, out, C, FF);
}

// round 4
// speedup vs baseline: 2.8864x; 1.4161x over previous
#include <cuda_runtime.h>
#include <math.h>
#include <cstdint>

// Problem constants
constexpr int Bb = 2;
constexpr int T  = 2048;
constexpr int C  = 1024;
constexpr int Hh = 16;
constexpr int Dd = 64;
constexpr int M  = Bb * T;       // 4096 tokens
constexpr int FF = 4 * C;        // 4096

// ---------------- scratch (static device memory; no allocation) -------------
__device__ float g_h  [M * C];       // LN output (tf32-rounded)
__device__ float g_q  [M * C];       // head layout [B,H,T,D] (tf32)
__device__ float g_k  [M * C];
__device__ float g_v  [M * C];
__device__ float g_y  [M * C];       // attn out (tf32-rounded)
__device__ float g_x1 [M * C];
__device__ float g_hid[(size_t)M * FF]; // MLP hidden (tf32-rounded)
// transposed weights, [N][K] layout, tf32-rounded
__device__ float g_wtq[C * C];
__device__ float g_wtk[C * C];
__device__ float g_wtv[C * C];
__device__ float g_wto[C * C];
__device__ float g_wt1[(size_t)C * FF];
__device__ float g_wt2[(size_t)C * FF];

// ---------------- helpers ----------------------------------------------------
__device__ __forceinline__ uint32_t smem_u32(const void* p) {
    uint32_t a;
    asm("{ .reg .u64 t; cvta.to.shared.u64 t, %1; cvt.u32.u64 %0, t; }"
        : "=r"(a) : "l"(p));
    return a;
}
__device__ __forceinline__ float to_tf32(float x) {
    float r;
    asm("cvt.rna.tf32.f32 %0, %1;" : "=f"(r) : "f"(x));
    return r;
}
__device__ __forceinline__ void cp_async16(uint32_t dst, const void* src) {
    asm volatile("cp.async.cg.shared.global [%0], [%1], 16;"
                 :: "r"(dst), "l"(src) : "memory");
}
#define CP_COMMIT() asm volatile("cp.async.commit_group;" ::: "memory")
#define CP_WAIT(n)  asm volatile("cp.async.wait_group %0;" :: "n"(n) : "memory")

__device__ __forceinline__ void mma_tf32(float* c, const uint32_t* a, const uint32_t* b) {
    asm volatile(
        "mma.sync.aligned.m16n8k8.row.col.f32.tf32.tf32.f32 "
        "{%0,%1,%2,%3}, {%4,%5,%6,%7}, {%8,%9}, {%0,%1,%2,%3};"
        : "+f"(c[0]), "+f"(c[1]), "+f"(c[2]), "+f"(c[3])
        : "r"(a[0]), "r"(a[1]), "r"(a[2]), "r"(a[3]), "r"(b[0]), "r"(b[1]));
}
__device__ __forceinline__ void ldm_x4(uint32_t* r, uint32_t addr) {
    asm volatile("ldmatrix.sync.aligned.m8n8.x4.shared.b16 {%0,%1,%2,%3}, [%4];"
        : "=r"(r[0]), "=r"(r[1]), "=r"(r[2]), "=r"(r[3]) : "r"(addr));
}

// ---------------- tf32 mma.sync GEMM, 128x128x32, ldmatrix frags -------------
// EPI: 0 = head-scatter +tf32, 1 = residual add, 2 = exact GELU (+tf32)
constexpr int LDK = 36;                        // padded row stride (floats)
constexpr int TILE_F = 128 * LDK;
constexpr int SMEM_SZ = 4 * TILE_F * 4;        // A0,B0,A1,B1 = 73728 B

template<int EPI>
__global__ __launch_bounds__(256)
void gemm_mma(const float* __restrict__ A,     // [M,K] row-major, tf32 values
              const float* __restrict__ Bt,    // [N,K] row-major, tf32 values
              const float* __restrict__ bias,
              const float* __restrict__ resid,
              float* __restrict__ out,
              int Nn, int Kk)
{
    extern __shared__ float sm[];
    const uint32_t sbase = smem_u32(sm);
    const int tid  = threadIdx.x;
    const int wid  = tid >> 5;
    const int lane = tid & 31;
    const int qr   = lane >> 2;
    const int qc   = lane & 3;
    const int bm = blockIdx.y * 128;
    const int bn = blockIdx.x * 128;
    const int warp_m = (wid & 1) * 64;
    const int warp_n = (wid >> 1) * 32;
    const int KT = Kk >> 5;

    // ldmatrix lane address components
    const int lane15 = lane & 15;
    const int lanehi = (lane >> 4) * 4;   // A-frag col sub-offset
    const int blrow  = lane & 7;          // B-frag row
    const int blcol  = (lane >> 3) * 4;   // B-frag col sub-offset (x4 over 16)

    const int aoff[2] = { 0, 2 * TILE_F };
    const int boff[2] = { TILE_F, 3 * TILE_F };

    auto issue_load = [&](int buf, int k0) {
        #pragma unroll
        for (int i = 0; i < 4; i++) {
            int idx = i * 256 + tid;
            int r = idx >> 3, c4 = idx & 7;
            cp_async16(sbase + (uint32_t)(aoff[buf] + r * LDK + c4 * 4) * 4,
                       &A[(size_t)(bm + r) * Kk + k0 + c4 * 4]);
        }
        #pragma unroll
        for (int i = 0; i < 4; i++) {
            int idx = i * 256 + tid;
            int r = idx >> 3, c4 = idx & 7;
            cp_async16(sbase + (uint32_t)(boff[buf] + r * LDK + c4 * 4) * 4,
                       &Bt[(size_t)(bn + r) * Kk + k0 + c4 * 4]);
        }
        CP_COMMIT();
    };

    float acc[4][4][4] = {};

    issue_load(0, 0);

    for (int kt = 0; kt < KT; kt++) {
        const int cur = kt & 1;
        if (kt + 1 < KT) issue_load(1 - cur, (kt + 1) * 32);
        if (kt + 1 < KT) { CP_WAIT(1); } else { CP_WAIT(0); }
        __syncthreads();

        // B fragments for all 4 ks, via x4 ks-pair loads
        uint32_t bfr[4][4][2];
        #pragma unroll
        for (int jn = 0; jn < 4; jn++) {
            #pragma unroll
            for (int ksp = 0; ksp < 2; ksp++) {
                uint32_t r[4];
                ldm_x4(r, sbase + (uint32_t)(boff[cur] +
                        (warp_n + jn * 8 + blrow) * LDK + ksp * 16 + blcol) * 4);
                bfr[jn][2*ksp  ][0] = r[0]; bfr[jn][2*ksp  ][1] = r[1];
                bfr[jn][2*ksp+1][0] = r[2]; bfr[jn][2*ksp+1][1] = r[3];
            }
        }
        #pragma unroll
        for (int ks = 0; ks < 4; ks++) {
            uint32_t a[4][4];
            #pragma unroll
            for (int im = 0; im < 4; im++)
                ldm_x4(a[im], sbase + (uint32_t)(aoff[cur] +
                        (warp_m + im * 16 + lane15) * LDK + ks * 8 + lanehi) * 4);
            #pragma unroll
            for (int im = 0; im < 4; im++)
                #pragma unroll
                for (int jn = 0; jn < 4; jn++)
                    mma_tf32(acc[im][jn], a[im], bfr[jn][ks]);
        }
        __syncthreads();
    }

    // epilogue
    #pragma unroll
    for (int im = 0; im < 4; im++) {
        const int r0 = bm + warp_m + im * 16 + qr;
        const int r1 = r0 + 8;
        #pragma unroll
        for (int jn = 0; jn < 4; jn++) {
            const int c0 = bn + warp_n + jn * 8 + qc * 2;
            const float2 bv = *(const float2*)&bias[c0];
            float2 v0, v1;
            v0.x = acc[im][jn][0] + bv.x;
            v0.y = acc[im][jn][1] + bv.y;
            v1.x = acc[im][jn][2] + bv.x;
            v1.y = acc[im][jn][3] + bv.y;
            if (EPI == 2) {
                v0.x = 0.5f * v0.x * (1.0f + erff(v0.x * 0.70710678118654752f));
                v0.y = 0.5f * v0.y * (1.0f + erff(v0.y * 0.70710678118654752f));
                v1.x = 0.5f * v1.x * (1.0f + erff(v1.x * 0.70710678118654752f));
                v1.y = 0.5f * v1.y * (1.0f + erff(v1.y * 0.70710678118654752f));
                v0.x = to_tf32(v0.x); v0.y = to_tf32(v0.y);
                v1.x = to_tf32(v1.x); v1.y = to_tf32(v1.y);
            }
            if (EPI == 1) {
                const float2 q0 = *(const float2*)&resid[(size_t)r0 * Nn + c0];
                const float2 q1 = *(const float2*)&resid[(size_t)r1 * Nn + c0];
                v0.x += q0.x; v0.y += q0.y;
                v1.x += q1.x; v1.y += q1.y;
            }
            if (EPI == 0) {
                v0.x = to_tf32(v0.x); v0.y = to_tf32(v0.y);   // feed attn MMA
                v1.x = to_tf32(v1.x); v1.y = to_tf32(v1.y);
                const int hi = c0 >> 6, dd = c0 & 63;
                {
                    const int bi = r0 >> 11, t = r0 & 2047;
                    *(float2*)&out[(((size_t)(bi * Hh + hi)) * T + t) * Dd + dd] = v0;
                }
                {
                    const int bi = r1 >> 11, t = r1 & 2047;
                    *(float2*)&out[(((size_t)(bi * Hh + hi)) * T + t) * Dd + dd] = v1;
                }
            } else {
                *(float2*)&out[(size_t)r0 * Nn + c0] = v0;
                *(float2*)&out[(size_t)r1 * Nn + c0] = v1;
            }
        }
    }
}

// ---------------- tensor-core flash attention (causal, tf32) -----------------
// CTA: 128 threads (4 warps), 64 q-rows per CTA (16 per warp)
constexpr int LDA = 68;                      // float stride, 16B-aligned, conflict-free
constexpr int SQ = 0;
constexpr int SK = 64 * LDA;
constexpr int SV = 2 * 64 * LDA;
constexpr int SP = 3 * 64 * LDA;             // + wid*16*LDA per warp
constexpr int SMEM_ATT = (3 * 64 * LDA + 4 * 16 * LDA) * 4;   // 69632 B

__global__ __launch_bounds__(128)
void attn_mma(const float* __restrict__ Q,
              const float* __restrict__ K,
              const float* __restrict__ V,
              float* __restrict__ Y)
{
    extern __shared__ float sm[];
    const uint32_t sbase = smem_u32(sm);
    const int tid  = threadIdx.x;
    const int wid  = tid >> 5;
    const int lane = tid & 31;
    const int qr   = lane >> 2;
    const int qc   = lane & 3;
    const int lane15 = lane & 15;
    const int lanehi = (lane >> 4) * 4;
    const int blrow  = lane & 7;
    const int blcol  = (lane >> 3) * 4;

    const int bh = blockIdx.y;
    const int qb = blockIdx.x;

    const float* Qp = Q + (size_t)bh * T * Dd + (size_t)qb * 64 * Dd;
    const float* Kp = K + (size_t)bh * T * Dd;
    const float* Vp = V + (size_t)bh * T * Dd;

    // load Q tile (scaled by 1/8; scale is exact, preserves tf32)
    #pragma unroll
    for (int i = 0; i < 8; i++) {
        int idx = i * 128 + tid;
        int r = idx >> 4, c4 = idx & 15;
        float4 qv = *(const float4*)&Qp[r * 64 + c4 * 4];
        qv.x *= 0.125f; qv.y *= 0.125f; qv.z *= 0.125f; qv.w *= 0.125f;
        *(float4*)&sm[SQ + r * LDA + c4 * 4] = qv;
    }
    __syncthreads();

    // Q fragments (A-layout), once
    uint32_t qf[8][4];
    #pragma unroll
    for (int kc = 0; kc < 8; kc++)
        ldm_x4(qf[kc], sbase + (uint32_t)(SQ + (wid * 16 + lane15) * LDA + kc * 8 + lanehi) * 4);

    float o[8][4] = {};
    float m0 = -1e30f, m1 = -1e30f, l0 = 0.0f, l1 = 0.0f;

    float* Pw = sm + SP + wid * 16 * LDA;
    const uint32_t pwbase = sbase + (uint32_t)(SP + wid * 16 * LDA) * 4;

    for (int kt = 0; kt <= qb; kt++) {
        // K tile: straight copy [j][d]
        #pragma unroll
        for (int i = 0; i < 8; i++) {
            int idx = i * 128 + tid;
            int r = idx >> 4, c4 = idx & 15;
            *(float4*)&sm[SK + r * LDA + c4 * 4] =
                *(const float4*)&Kp[((size_t)(kt * 64 + r)) * 64 + c4 * 4];
        }
        // V tile: transposed -> Vt[d][j]; lane remap keeps STS conflict-free
        #pragma unroll
        for (int i = 0; i < 8; i++) {
            int vr = (tid & 15) + 16 * (i & 3);          // source row j
            int c4 = (tid >> 4) + 8 * (i >> 2);          // source col group
            float4 vv = *(const float4*)&Vp[((size_t)(kt * 64 + vr)) * 64 + c4 * 4];
            sm[SV + (c4 * 4 + 0) * LDA + vr] = vv.x;
            sm[SV + (c4 * 4 + 1) * LDA + vr] = vv.y;
            sm[SV + (c4 * 4 + 2) * LDA + vr] = vv.z;
            sm[SV + (c4 * 4 + 3) * LDA + vr] = vv.w;
        }
        __syncthreads();

        // ---- S = Q K^T (per warp: 16x64) ----
        float sacc[8][4];
        #pragma unroll
        for (int jb = 0; jb < 8; jb++) {
            sacc[jb][0] = sacc[jb][1] = sacc[jb][2] = sacc[jb][3] = 0.0f;
            #pragma unroll
            for (int kcp = 0; kcp < 4; kcp++) {
                uint32_t r[4];
                ldm_x4(r, sbase + (uint32_t)(SK + (jb * 8 + blrow) * LDA + kcp * 16 + blcol) * 4);
                uint32_t b0[2] = { r[0], r[1] };
                uint32_t b1[2] = { r[2], r[3] };
                mma_tf32(sacc[jb], qf[2 * kcp],     b0);
                mma_tf32(sacc[jb], qf[2 * kcp + 1], b1);
            }
        }

        // causal mask on diagonal tile (local row/col comparison valid: same tile base)
        if (kt == qb) {
            const int row0 = wid * 16 + qr;
            const int row1 = row0 + 8;
            #pragma unroll
            for (int jb = 0; jb < 8; jb++) {
                const int cb = jb * 8 + 2 * qc;
                if (cb     > row0) sacc[jb][0] = -1e30f;
                if (cb + 1 > row0) sacc[jb][1] = -1e30f;
                if (cb     > row1) sacc[jb][2] = -1e30f;
                if (cb + 1 > row1) sacc[jb][3] = -1e30f;
            }
        }

        // ---- online softmax ----
        float r0 = -1e30f, r1 = -1e30f;
        #pragma unroll
        for (int jb = 0; jb < 8; jb++) {
            r0 = fmaxf(r0, fmaxf(sacc[jb][0], sacc[jb][1]));
            r1 = fmaxf(r1, fmaxf(sacc[jb][2], sacc[jb][3]));
        }
        r0 = fmaxf(r0, __shfl_xor_sync(0xffffffffu, r0, 1));
        r0 = fmaxf(r0, __shfl_xor_sync(0xffffffffu, r0, 2));
        r1 = fmaxf(r1, __shfl_xor_sync(0xffffffffu, r1, 1));
        r1 = fmaxf(r1, __shfl_xor_sync(0xffffffffu, r1, 2));

        const float mn0 = fmaxf(m0, r0), mn1 = fmaxf(m1, r1);
        const float cr0 = __expf(m0 - mn0), cr1 = __expf(m1 - mn1);
        m0 = mn0; m1 = mn1;
        l0 *= cr0; l1 *= cr1;
        #pragma unroll
        for (int db = 0; db < 8; db++) {
            o[db][0] *= cr0; o[db][1] *= cr0;
            o[db][2] *= cr1; o[db][3] *= cr1;
        }

        // P = exp(S - m), accumulate l, stage to smem (tf32-rounded)
        #pragma unroll
        for (int jb = 0; jb < 8; jb++) {
            float p0 = __expf(sacc[jb][0] - m0);
            float p1 = __expf(sacc[jb][1] - m0);
            float p2 = __expf(sacc[jb][2] - m1);
            float p3 = __expf(sacc[jb][3] - m1);
            l0 += p0 + p1; l1 += p2 + p3;
            float2 w0 = { to_tf32(p0), to_tf32(p1) };
            float2 w1 = { to_tf32(p2), to_tf32(p3) };
            *(float2*)&Pw[qr * LDA + jb * 8 + 2 * qc]       = w0;
            *(float2*)&Pw[(qr + 8) * LDA + jb * 8 + 2 * qc] = w1;
        }
        __syncwarp();

        // P fragments (A-layout)
        uint32_t pf[8][4];
        #pragma unroll
        for (int kc = 0; kc < 8; kc++)
            ldm_x4(pf[kc], pwbase + (uint32_t)(lane15 * LDA + kc * 8 + lanehi) * 4);

        // ---- O += P V  (B operand = Vt[d][j]) ----
        #pragma unroll
        for (int db = 0; db < 8; db++) {
            #pragma unroll
            for (int kcp = 0; kcp < 4; kcp++) {
                uint32_t r[4];
                ldm_x4(r, sbase + (uint32_t)(SV + (db * 8 + blrow) * LDA + kcp * 16 + blcol) * 4);
                uint32_t b0[2] = { r[0], r[1] };
                uint32_t b1[2] = { r[2], r[3] };
                mma_tf32(o[db], pf[2 * kcp],     b0);
                mma_tf32(o[db], pf[2 * kcp + 1], b1);
            }
        }
        __syncthreads();   // protect K/Vt before next iteration overwrites
    }

    // finalize: reduce l across the 4 lanes of each row group
    l0 += __shfl_xor_sync(0xffffffffu, l0, 1);
    l0 += __shfl_xor_sync(0xffffffffu, l0, 2);
    l1 += __shfl_xor_sync(0xffffffffu, l1, 1);
    l1 += __shfl_xor_sync(0xffffffffu, l1, 2);
    const float inv0 = 1.0f / l0, inv1 = 1.0f / l1;

    const int bi = bh >> 4, hi = bh & 15;
    const int q0 = qb * 64 + wid * 16 + qr;
    const int q1 = q0 + 8;
    float* y0 = Y + ((size_t)(bi * T + q0)) * C + hi * Dd;
    float* y1 = Y + ((size_t)(bi * T + q1)) * C + hi * Dd;
    #pragma unroll
    for (int db = 0; db < 8; db++) {
        const int d = db * 8 + 2 * qc;
        float2 a = { to_tf32(o[db][0] * inv0), to_tf32(o[db][1] * inv0) };
        float2 b = { to_tf32(o[db][2] * inv1), to_tf32(o[db][3] * inv1) };
        *(float2*)&y0[d] = a;
        *(float2*)&y1[d] = b;
    }
}

// ---------------- weight transpose [R,Cc] -> [Cc,R], tf32 rounding ----------
__global__ void transpose_kernel(const float* __restrict__ in, float* __restrict__ out,
                                 int R, int Cc)
{
    __shared__ float tile[32][33];
    int x = blockIdx.x * 32 + threadIdx.x;
    int y = blockIdx.y * 32 + threadIdx.y;
    #pragma unroll
    for (int j = 0; j < 32; j += 8)
        tile[threadIdx.y + j][threadIdx.x] = to_tf32(in[(size_t)(y + j) * Cc + x]);
    __syncthreads();
    int xo = blockIdx.y * 32 + threadIdx.x;
    int yo = blockIdx.x * 32 + threadIdx.y;
    #pragma unroll
    for (int j = 0; j < 32; j += 8)
        out[(size_t)(yo + j) * R + xo] = tile[threadIdx.x][threadIdx.y + j];
}

// ---------------- LayerNorm (tf32-rounded output) ----------------------------
__global__ void ln_kernel(const float* __restrict__ X,
                          const float* __restrict__ w,
                          const float* __restrict__ b,
                          float* __restrict__ out)
{
    int row = blockIdx.x;
    int tid = threadIdx.x;
    const float4 xv = *(const float4*)&X[(size_t)row * C + tid * 4];

    float s  = xv.x + xv.y + xv.z + xv.w;
    float sq = xv.x*xv.x + xv.y*xv.y + xv.z*xv.z + xv.w*xv.w;
    #pragma unroll
    for (int off = 16; off > 0; off >>= 1) {
        s  += __shfl_xor_sync(0xffffffffu, s,  off);
        sq += __shfl_xor_sync(0xffffffffu, sq, off);
    }
    __shared__ float ss[8], ssq[8];
    __shared__ float mu_s, rstd_s;
    int lane = tid & 31, wid = tid >> 5;
    if (lane == 0) { ss[wid] = s; ssq[wid] = sq; }
    __syncthreads();
    if (tid == 0) {
        float ts = 0.f, tq = 0.f;
        #pragma unroll
        for (int i = 0; i < 8; i++) { ts += ss[i]; tq += ssq[i]; }
        float mu  = ts * (1.0f / C);
        float var = tq * (1.0f / C) - mu * mu;
        mu_s = mu; rstd_s = rsqrtf(var + 1e-5f);
    }
    __syncthreads();
    float mu = mu_s, r = rstd_s;
    const float4 wv = *(const float4*)&w[tid * 4];
    const float4 bv = *(const float4*)&b[tid * 4];
    float4 o;
    o.x = to_tf32((xv.x - mu) * r * wv.x + bv.x);
    o.y = to_tf32((xv.y - mu) * r * wv.y + bv.y);
    o.z = to_tf32((xv.z - mu) * r * wv.z + bv.z);
    o.w = to_tf32((xv.w - mu) * r * wv.w + bv.w);
    *(float4*)&out[(size_t)row * C + tid * 4] = o;
}

// ---------------- launcher ----------------------------------------------------
extern "C" void kernel_launch(void* const* d_in, const int* in_sizes, int n_in,
                              void* d_out, int out_size)
{
    const float* x     = (const float*)d_in[0];
    const float* ln1_w = (const float*)d_in[1];
    const float* ln1_b = (const float*)d_in[2];
    const float* wq    = (const float*)d_in[3];
    const float* bq    = (const float*)d_in[4];
    const float* wk    = (const float*)d_in[5];
    const float* bk    = (const float*)d_in[6];
    const float* wv    = (const float*)d_in[7];
    const float* bv    = (const float*)d_in[8];
    const float* wo    = (const float*)d_in[9];
    const float* bo    = (const float*)d_in[10];
    const float* ln2_w = (const float*)d_in[11];
    const float* ln2_b = (const float*)d_in[12];
    const float* w1    = (const float*)d_in[13];
    const float* b1    = (const float*)d_in[14];
    const float* w2    = (const float*)d_in[15];
    const float* b2    = (const float*)d_in[16];

    float *h, *q, *k, *v, *y, *x1, *hid;
    float *wtq, *wtk, *wtv, *wto, *wt1, *wt2;
    cudaGetSymbolAddress((void**)&h,   g_h);
    cudaGetSymbolAddress((void**)&q,   g_q);
    cudaGetSymbolAddress((void**)&k,   g_k);
    cudaGetSymbolAddress((void**)&v,   g_v);
    cudaGetSymbolAddress((void**)&y,   g_y);
    cudaGetSymbolAddress((void**)&x1,  g_x1);
    cudaGetSymbolAddress((void**)&hid, g_hid);
    cudaGetSymbolAddress((void**)&wtq, g_wtq);
    cudaGetSymbolAddress((void**)&wtk, g_wtk);
    cudaGetSymbolAddress((void**)&wtv, g_wtv);
    cudaGetSymbolAddress((void**)&wto, g_wto);
    cudaGetSymbolAddress((void**)&wt1, g_wt1);
    cudaGetSymbolAddress((void**)&wt2, g_wt2);

    float* out = (float*)d_out;

    cudaFuncSetAttribute(gemm_mma<0>, cudaFuncAttributeMaxDynamicSharedMemorySize, SMEM_SZ);
    cudaFuncSetAttribute(gemm_mma<1>, cudaFuncAttributeMaxDynamicSharedMemorySize, SMEM_SZ);
    cudaFuncSetAttribute(gemm_mma<2>, cudaFuncAttributeMaxDynamicSharedMemorySize, SMEM_SZ);
    cudaFuncSetAttribute(attn_mma,    cudaFuncAttributeMaxDynamicSharedMemorySize, SMEM_ATT);

    dim3 tb(32, 8);
    transpose_kernel<<<dim3(C/32,  C/32),  tb>>>(wq, wtq, C,  C);
    transpose_kernel<<<dim3(C/32,  C/32),  tb>>>(wk, wtk, C,  C);
    transpose_kernel<<<dim3(C/32,  C/32),  tb>>>(wv, wtv, C,  C);
    transpose_kernel<<<dim3(C/32,  C/32),  tb>>>(wo, wto, C,  C);
    transpose_kernel<<<dim3(FF/32, C/32),  tb>>>(w1, wt1, C,  FF);
    transpose_kernel<<<dim3(C/32,  FF/32), tb>>>(w2, wt2, FF, C);

    ln_kernel<<<M, 256>>>(x, ln1_w, ln1_b, h);
    gemm_mma<0><<<dim3(C/128,  M/128), 256, SMEM_SZ>>>(h, wtq, bq, nullptr, q, C, C);
    gemm_mma<0><<<dim3(C/128,  M/128), 256, SMEM_SZ>>>(h, wtk, bk, nullptr, k, C, C);
    gemm_mma<0><<<dim3(C/128,  M/128), 256, SMEM_SZ>>>(h, wtv, bv, nullptr, v, C, C);
    attn_mma<<<dim3(T/64, Bb*Hh), 128, SMEM_ATT>>>(q, k, v, y);
    gemm_mma<1><<<dim3(C/128,  M/128), 256, SMEM_SZ>>>(y, wto, bo, x, x1, C, C);
    ln_kernel<<<M, 256>>>(x1, ln2_w, ln2_b, h);
    gemm_mma<2><<<dim3(FF/128, M/128), 256, SMEM_SZ>>>(h, wt1, b1, nullptr, hid, FF, C);
    gemm_mma<1><<<dim3(C/128,  M/128), 256, SMEM_SZ>>>(hid, wt2, b2, x1, out, C, FF);
}

// round 5
// speedup vs baseline: 3.1479x; 1.0906x over previous
#include <cuda_runtime.h>
#include <math.h>
#include <cstdint>

// Problem constants
constexpr int Bb = 2;
constexpr int T  = 2048;
constexpr int C  = 1024;
constexpr int Hh = 16;
constexpr int Dd = 64;
constexpr int M  = Bb * T;       // 4096 tokens
constexpr int FF = 4 * C;        // 4096

// ---------------- scratch (static device memory; no allocation) -------------
__device__ float g_h  [M * C];            // LN output (tf32-rounded)
__device__ float g_qkv[(size_t)3 * M * C]; // q|k|v, head layout [B,H,T,D] each
__device__ float g_y  [M * C];            // attn out (tf32-rounded)
__device__ float g_x1 [M * C];
__device__ float g_hid[(size_t)M * FF];   // MLP hidden (tf32-rounded)
// transposed weights, [N][K] layout, tf32-rounded
__device__ float g_wtqkv[(size_t)3 * C * C];  // wq^T | wk^T | wv^T rows 0..3071
__device__ float g_bqkv [3 * C];
__device__ float g_wto[C * C];
__device__ float g_wt1[(size_t)C * FF];
__device__ float g_wt2[(size_t)C * FF];

// ---------------- helpers ----------------------------------------------------
__device__ __forceinline__ uint32_t smem_u32(const void* p) {
    uint32_t a;
    asm("{ .reg .u64 t; cvta.to.shared.u64 t, %1; cvt.u32.u64 %0, t; }"
        : "=r"(a) : "l"(p));
    return a;
}
__device__ __forceinline__ float to_tf32(float x) {
    float r;
    asm("cvt.rna.tf32.f32 %0, %1;" : "=f"(r) : "f"(x));
    return r;
}
__device__ __forceinline__ void cp_async16(uint32_t dst, const void* src) {
    asm volatile("cp.async.cg.shared.global [%0], [%1], 16;"
                 :: "r"(dst), "l"(src) : "memory");
}
#define CP_COMMIT() asm volatile("cp.async.commit_group;" ::: "memory")
#define CP_WAIT(n)  asm volatile("cp.async.wait_group %0;" :: "n"(n) : "memory")

__device__ __forceinline__ void mma_tf32(float* c, const uint32_t* a, const uint32_t* b) {
    asm volatile(
        "mma.sync.aligned.m16n8k8.row.col.f32.tf32.tf32.f32 "
        "{%0,%1,%2,%3}, {%4,%5,%6,%7}, {%8,%9}, {%0,%1,%2,%3};"
        : "+f"(c[0]), "+f"(c[1]), "+f"(c[2]), "+f"(c[3])
        : "r"(a[0]), "r"(a[1]), "r"(a[2]), "r"(a[3]), "r"(b[0]), "r"(b[1]));
}
__device__ __forceinline__ void ldm_x4(uint32_t* r, uint32_t addr) {
    asm volatile("ldmatrix.sync.aligned.m8n8.x4.shared.b16 {%0,%1,%2,%3}, [%4];"
        : "=r"(r[0]), "=r"(r[1]), "=r"(r[2]), "=r"(r[3]) : "r"(addr));
}

// ---------------- tf32 mma.sync GEMM, 128x128x32, 3-stage pipeline ----------
// EPI: 0 = fused-QKV head-scatter (+tf32), 1 = residual add, 2 = exact GELU (+tf32)
constexpr int LDK = 36;                        // padded row stride (floats)
constexpr int TILE_F = 128 * LDK;              // floats per A/B tile
constexpr int NSTAGE = 3;
constexpr int SMEM_SZ = NSTAGE * 2 * TILE_F * 4;   // 110592 B

template<int EPI>
__global__ __launch_bounds__(256)
void gemm_mma(const float* __restrict__ A,     // [M,K] row-major, tf32 values
              const float* __restrict__ Bt,    // [N,K] row-major, tf32 values
              const float* __restrict__ bias,
              const float* __restrict__ resid,
              float* __restrict__ out,
              int Nn, int Kk)
{
    extern __shared__ float sm[];
    const uint32_t sbase = smem_u32(sm);
    const int tid  = threadIdx.x;
    const int wid  = tid >> 5;
    const int lane = tid & 31;
    const int qr   = lane >> 2;
    const int qc   = lane & 3;
    const int bm = blockIdx.y * 128;
    const int bn = blockIdx.x * 128;
    const int warp_m = (wid & 1) * 64;
    const int warp_n = (wid >> 1) * 32;
    const int KT = Kk >> 5;

    const int lane15 = lane & 15;
    const int lanehi = (lane >> 4) * 4;
    const int blrow  = lane & 7;
    const int blcol  = (lane >> 3) * 4;

    // stage s: A at 2s*TILE_F, B at (2s+1)*TILE_F
    auto issue_load = [&](int buf, int k0) {
        const int ao = 2 * buf * TILE_F;
        const int bo = ao + TILE_F;
        #pragma unroll
        for (int i = 0; i < 4; i++) {
            int idx = i * 256 + tid;
            int r = idx >> 3, c4 = idx & 7;
            cp_async16(sbase + (uint32_t)(ao + r * LDK + c4 * 4) * 4,
                       &A[(size_t)(bm + r) * Kk + k0 + c4 * 4]);
        }
        #pragma unroll
        for (int i = 0; i < 4; i++) {
            int idx = i * 256 + tid;
            int r = idx >> 3, c4 = idx & 7;
            cp_async16(sbase + (uint32_t)(bo + r * LDK + c4 * 4) * 4,
                       &Bt[(size_t)(bn + r) * Kk + k0 + c4 * 4]);
        }
        CP_COMMIT();
    };

    float acc[4][4][4] = {};

    issue_load(0, 0);
    issue_load(1, 32);

    for (int kt = 0; kt < KT; kt++) {
        const int cur = kt % NSTAGE;
        CP_WAIT(1);                 // stage kt retired (FIFO; empty commits keep count)
        __syncthreads();            // all threads' reads of stage (kt-1)%3 done; data visible
        if (kt + 2 < KT) issue_load((kt + 2) % NSTAGE, (kt + 2) * 32);
        else             CP_COMMIT();   // empty group keeps wait_group accounting exact

        const int ao = 2 * cur * TILE_F;
        const int bo = ao + TILE_F;

        // B fragments for all 4 ks, via x4 ks-pair loads
        uint32_t bfr[4][4][2];
        #pragma unroll
        for (int jn = 0; jn < 4; jn++) {
            #pragma unroll
            for (int ksp = 0; ksp < 2; ksp++) {
                uint32_t r[4];
                ldm_x4(r, sbase + (uint32_t)(bo +
                        (warp_n + jn * 8 + blrow) * LDK + ksp * 16 + blcol) * 4);
                bfr[jn][2*ksp  ][0] = r[0]; bfr[jn][2*ksp  ][1] = r[1];
                bfr[jn][2*ksp+1][0] = r[2]; bfr[jn][2*ksp+1][1] = r[3];
            }
        }
        #pragma unroll
        for (int ks = 0; ks < 4; ks++) {
            uint32_t a[4][4];
            #pragma unroll
            for (int im = 0; im < 4; im++)
                ldm_x4(a[im], sbase + (uint32_t)(ao +
                        (warp_m + im * 16 + lane15) * LDK + ks * 8 + lanehi) * 4);
            #pragma unroll
            for (int im = 0; im < 4; im++)
                #pragma unroll
                for (int jn = 0; jn < 4; jn++)
                    mma_tf32(acc[im][jn], a[im], bfr[jn][ks]);
        }
    }

    // epilogue
    #pragma unroll
    for (int im = 0; im < 4; im++) {
        const int r0 = bm + warp_m + im * 16 + qr;
        const int r1 = r0 + 8;
        #pragma unroll
        for (int jn = 0; jn < 4; jn++) {
            const int c0 = bn + warp_n + jn * 8 + qc * 2;
            const float2 bv = *(const float2*)&bias[c0];
            float2 v0, v1;
            v0.x = acc[im][jn][0] + bv.x;
            v0.y = acc[im][jn][1] + bv.y;
            v1.x = acc[im][jn][2] + bv.x;
            v1.y = acc[im][jn][3] + bv.y;
            if (EPI == 2) {
                v0.x = 0.5f * v0.x * (1.0f + erff(v0.x * 0.70710678118654752f));
                v0.y = 0.5f * v0.y * (1.0f + erff(v0.y * 0.70710678118654752f));
                v1.x = 0.5f * v1.x * (1.0f + erff(v1.x * 0.70710678118654752f));
                v1.y = 0.5f * v1.y * (1.0f + erff(v1.y * 0.70710678118654752f));
                v0.x = to_tf32(v0.x); v0.y = to_tf32(v0.y);
                v1.x = to_tf32(v1.x); v1.y = to_tf32(v1.y);
            }
            if (EPI == 1) {
                const float2 q0 = *(const float2*)&resid[(size_t)r0 * Nn + c0];
                const float2 q1 = *(const float2*)&resid[(size_t)r1 * Nn + c0];
                v0.x += q0.x; v0.y += q0.y;
                v1.x += q1.x; v1.y += q1.y;
            }
            if (EPI == 0) {
                v0.x = to_tf32(v0.x); v0.y = to_tf32(v0.y);   // feed attn MMA
                v1.x = to_tf32(v1.x); v1.y = to_tf32(v1.y);
                const int mat = c0 >> 10;          // 0=q 1=k 2=v
                const int cc  = c0 & 1023;
                const int hi = cc >> 6, dd = cc & 63;
                float* ob = out + (size_t)mat * M * C;
                {
                    const int bi = r0 >> 11, t = r0 & 2047;
                    *(float2*)&ob[(((size_t)(bi * Hh + hi)) * T + t) * Dd + dd] = v0;
                }
                {
                    const int bi = r1 >> 11, t = r1 & 2047;
                    *(float2*)&ob[(((size_t)(bi * Hh + hi)) * T + t) * Dd + dd] = v1;
                }
            } else {
                *(float2*)&out[(size_t)r0 * Nn + c0] = v0;
                *(float2*)&out[(size_t)r1 * Nn + c0] = v1;
            }
        }
    }
}

// ---------------- tensor-core flash attention (causal, tf32) -----------------
constexpr int LDA = 68;
constexpr int SQ = 0;
constexpr int SK = 64 * LDA;
constexpr int SV = 2 * 64 * LDA;
constexpr int SP = 3 * 64 * LDA;
constexpr int SMEM_ATT = (3 * 64 * LDA + 4 * 16 * LDA) * 4;

__global__ __launch_bounds__(128)
void attn_mma(const float* __restrict__ Q,
              const float* __restrict__ K,
              const float* __restrict__ V,
              float* __restrict__ Y)
{
    extern __shared__ float sm[];
    const uint32_t sbase = smem_u32(sm);
    const int tid  = threadIdx.x;
    const int wid  = tid >> 5;
    const int lane = tid & 31;
    const int qr   = lane >> 2;
    const int qc   = lane & 3;
    const int lane15 = lane & 15;
    const int lanehi = (lane >> 4) * 4;
    const int blrow  = lane & 7;
    const int blcol  = (lane >> 3) * 4;

    const int bh = blockIdx.y;
    const int qb = blockIdx.x;

    const float* Qp = Q + (size_t)bh * T * Dd + (size_t)qb * 64 * Dd;
    const float* Kp = K + (size_t)bh * T * Dd;
    const float* Vp = V + (size_t)bh * T * Dd;

    #pragma unroll
    for (int i = 0; i < 8; i++) {
        int idx = i * 128 + tid;
        int r = idx >> 4, c4 = idx & 15;
        float4 qv = *(const float4*)&Qp[r * 64 + c4 * 4];
        qv.x *= 0.125f; qv.y *= 0.125f; qv.z *= 0.125f; qv.w *= 0.125f;
        *(float4*)&sm[SQ + r * LDA + c4 * 4] = qv;
    }
    __syncthreads();

    uint32_t qf[8][4];
    #pragma unroll
    for (int kc = 0; kc < 8; kc++)
        ldm_x4(qf[kc], sbase + (uint32_t)(SQ + (wid * 16 + lane15) * LDA + kc * 8 + lanehi) * 4);

    float o[8][4] = {};
    float m0 = -1e30f, m1 = -1e30f, l0 = 0.0f, l1 = 0.0f;

    float* Pw = sm + SP + wid * 16 * LDA;
    const uint32_t pwbase = sbase + (uint32_t)(SP + wid * 16 * LDA) * 4;

    for (int kt = 0; kt <= qb; kt++) {
        #pragma unroll
        for (int i = 0; i < 8; i++) {
            int idx = i * 128 + tid;
            int r = idx >> 4, c4 = idx & 15;
            *(float4*)&sm[SK + r * LDA + c4 * 4] =
                *(const float4*)&Kp[((size_t)(kt * 64 + r)) * 64 + c4 * 4];
        }
        #pragma unroll
        for (int i = 0; i < 8; i++) {
            int vr = (tid & 15) + 16 * (i & 3);
            int c4 = (tid >> 4) + 8 * (i >> 2);
            float4 vv = *(const float4*)&Vp[((size_t)(kt * 64 + vr)) * 64 + c4 * 4];
            sm[SV + (c4 * 4 + 0) * LDA + vr] = vv.x;
            sm[SV + (c4 * 4 + 1) * LDA + vr] = vv.y;
            sm[SV + (c4 * 4 + 2) * LDA + vr] = vv.z;
            sm[SV + (c4 * 4 + 3) * LDA + vr] = vv.w;
        }
        __syncthreads();

        float sacc[8][4];
        #pragma unroll
        for (int jb = 0; jb < 8; jb++) {
            sacc[jb][0] = sacc[jb][1] = sacc[jb][2] = sacc[jb][3] = 0.0f;
            #pragma unroll
            for (int kcp = 0; kcp < 4; kcp++) {
                uint32_t r[4];
                ldm_x4(r, sbase + (uint32_t)(SK + (jb * 8 + blrow) * LDA + kcp * 16 + blcol) * 4);
                uint32_t b0[2] = { r[0], r[1] };
                uint32_t b1[2] = { r[2], r[3] };
                mma_tf32(sacc[jb], qf[2 * kcp],     b0);
                mma_tf32(sacc[jb], qf[2 * kcp + 1], b1);
            }
        }

        if (kt == qb) {
            const int row0 = wid * 16 + qr;
            const int row1 = row0 + 8;
            #pragma unroll
            for (int jb = 0; jb < 8; jb++) {
                const int cb = jb * 8 + 2 * qc;
                if (cb     > row0) sacc[jb][0] = -1e30f;
                if (cb + 1 > row0) sacc[jb][1] = -1e30f;
                if (cb     > row1) sacc[jb][2] = -1e30f;
                if (cb + 1 > row1) sacc[jb][3] = -1e30f;
            }
        }

        float r0 = -1e30f, r1 = -1e30f;
        #pragma unroll
        for (int jb = 0; jb < 8; jb++) {
            r0 = fmaxf(r0, fmaxf(sacc[jb][0], sacc[jb][1]));
            r1 = fmaxf(r1, fmaxf(sacc[jb][2], sacc[jb][3]));
        }
        r0 = fmaxf(r0, __shfl_xor_sync(0xffffffffu, r0, 1));
        r0 = fmaxf(r0, __shfl_xor_sync(0xffffffffu, r0, 2));
        r1 = fmaxf(r1, __shfl_xor_sync(0xffffffffu, r1, 1));
        r1 = fmaxf(r1, __shfl_xor_sync(0xffffffffu, r1, 2));

        const float mn0 = fmaxf(m0, r0), mn1 = fmaxf(m1, r1);
        const float cr0 = __expf(m0 - mn0), cr1 = __expf(m1 - mn1);
        m0 = mn0; m1 = mn1;
        l0 *= cr0; l1 *= cr1;
        #pragma unroll
        for (int db = 0; db < 8; db++) {
            o[db][0] *= cr0; o[db][1] *= cr0;
            o[db][2] *= cr1; o[db][3] *= cr1;
        }

        #pragma unroll
        for (int jb = 0; jb < 8; jb++) {
            float p0 = __expf(sacc[jb][0] - m0);
            float p1 = __expf(sacc[jb][1] - m0);
            float p2 = __expf(sacc[jb][2] - m1);
            float p3 = __expf(sacc[jb][3] - m1);
            l0 += p0 + p1; l1 += p2 + p3;
            float2 w0 = { to_tf32(p0), to_tf32(p1) };
            float2 w1 = { to_tf32(p2), to_tf32(p3) };
            *(float2*)&Pw[qr * LDA + jb * 8 + 2 * qc]       = w0;
            *(float2*)&Pw[(qr + 8) * LDA + jb * 8 + 2 * qc] = w1;
        }
        __syncwarp();

        uint32_t pf[8][4];
        #pragma unroll
        for (int kc = 0; kc < 8; kc++)
            ldm_x4(pf[kc], pwbase + (uint32_t)(lane15 * LDA + kc * 8 + lanehi) * 4);

        #pragma unroll
        for (int db = 0; db < 8; db++) {
            #pragma unroll
            for (int kcp = 0; kcp < 4; kcp++) {
                uint32_t r[4];
                ldm_x4(r, sbase + (uint32_t)(SV + (db * 8 + blrow) * LDA + kcp * 16 + blcol) * 4);
                uint32_t b0[2] = { r[0], r[1] };
                uint32_t b1[2] = { r[2], r[3] };
                mma_tf32(o[db], pf[2 * kcp],     b0);
                mma_tf32(o[db], pf[2 * kcp + 1], b1);
            }
        }
        __syncthreads();
    }

    l0 += __shfl_xor_sync(0xffffffffu, l0, 1);
    l0 += __shfl_xor_sync(0xffffffffu, l0, 2);
    l1 += __shfl_xor_sync(0xffffffffu, l1, 1);
    l1 += __shfl_xor_sync(0xffffffffu, l1, 2);
    const float inv0 = 1.0f / l0, inv1 = 1.0f / l1;

    const int bi = bh >> 4, hi = bh & 15;
    const int q0 = qb * 64 + wid * 16 + qr;
    const int q1 = q0 + 8;
    float* y0 = Y + ((size_t)(bi * T + q0)) * C + hi * Dd;
    float* y1 = Y + ((size_t)(bi * T + q1)) * C + hi * Dd;
    #pragma unroll
    for (int db = 0; db < 8; db++) {
        const int d = db * 8 + 2 * qc;
        float2 a = { to_tf32(o[db][0] * inv0), to_tf32(o[db][1] * inv0) };
        float2 b = { to_tf32(o[db][2] * inv1), to_tf32(o[db][3] * inv1) };
        *(float2*)&y0[d] = a;
        *(float2*)&y1[d] = b;
    }
}

// ---------------- weight transpose [R,Cc] -> [Cc,R], tf32 rounding ----------
__global__ void transpose_kernel(const float* __restrict__ in, float* __restrict__ out,
                                 int R, int Cc)
{
    __shared__ float tile[32][33];
    int x = blockIdx.x * 32 + threadIdx.x;
    int y = blockIdx.y * 32 + threadIdx.y;
    #pragma unroll
    for (int j = 0; j < 32; j += 8)
        tile[threadIdx.y + j][threadIdx.x] = to_tf32(in[(size_t)(y + j) * Cc + x]);
    __syncthreads();
    int xo = blockIdx.y * 32 + threadIdx.x;
    int yo = blockIdx.x * 32 + threadIdx.y;
    #pragma unroll
    for (int j = 0; j < 32; j += 8)
        out[(size_t)(yo + j) * R + xo] = tile[threadIdx.x][threadIdx.y + j];
}

// pack q/k/v biases into one [3072] buffer
__global__ void pack_bias(const float* __restrict__ a, const float* __restrict__ b,
                          const float* __restrict__ c, float* __restrict__ out)
{
    int i = threadIdx.x;
    const float* src = (blockIdx.x == 0) ? a : (blockIdx.x == 1) ? b : c;
    out[blockIdx.x * C + i] = src[i];
}

// ---------------- LayerNorm (tf32-rounded output) ----------------------------
__global__ void ln_kernel(const float* __restrict__ X,
                          const float* __restrict__ w,
                          const float* __restrict__ b,
                          float* __restrict__ out)
{
    int row = blockIdx.x;
    int tid = threadIdx.x;
    const float4 xv = *(const float4*)&X[(size_t)row * C + tid * 4];

    float s  = xv.x + xv.y + xv.z + xv.w;
    float sq = xv.x*xv.x + xv.y*xv.y + xv.z*xv.z + xv.w*xv.w;
    #pragma unroll
    for (int off = 16; off > 0; off >>= 1) {
        s  += __shfl_xor_sync(0xffffffffu, s,  off);
        sq += __shfl_xor_sync(0xffffffffu, sq, off);
    }
    __shared__ float ss[8], ssq[8];
    __shared__ float mu_s, rstd_s;
    int lane = tid & 31, wid = tid >> 5;
    if (lane == 0) { ss[wid] = s; ssq[wid] = sq; }
    __syncthreads();
    if (tid == 0) {
        float ts = 0.f, tq = 0.f;
        #pragma unroll
        for (int i = 0; i < 8; i++) { ts += ss[i]; tq += ssq[i]; }
        float mu  = ts * (1.0f / C);
        float var = tq * (1.0f / C) - mu * mu;
        mu_s = mu; rstd_s = rsqrtf(var + 1e-5f);
    }
    __syncthreads();
    float mu = mu_s, r = rstd_s;
    const float4 wv = *(const float4*)&w[tid * 4];
    const float4 bv = *(const float4*)&b[tid * 4];
    float4 o;
    o.x = to_tf32((xv.x - mu) * r * wv.x + bv.x);
    o.y = to_tf32((xv.y - mu) * r * wv.y + bv.y);
    o.z = to_tf32((xv.z - mu) * r * wv.z + bv.z);
    o.w = to_tf32((xv.w - mu) * r * wv.w + bv.w);
    *(float4*)&out[(size_t)row * C + tid * 4] = o;
}

// ---------------- launcher ----------------------------------------------------
extern "C" void kernel_launch(void* const* d_in, const int* in_sizes, int n_in,
                              void* d_out, int out_size)
{
    const float* x     = (const float*)d_in[0];
    const float* ln1_w = (const float*)d_in[1];
    const float* ln1_b = (const float*)d_in[2];
    const float* wq    = (const float*)d_in[3];
    const float* bq    = (const float*)d_in[4];
    const float* wk    = (const float*)d_in[5];
    const float* bk    = (const float*)d_in[6];
    const float* wv    = (const float*)d_in[7];
    const float* bv    = (const float*)d_in[8];
    const float* wo    = (const float*)d_in[9];
    const float* bo    = (const float*)d_in[10];
    const float* ln2_w = (const float*)d_in[11];
    const float* ln2_b = (const float*)d_in[12];
    const float* w1    = (const float*)d_in[13];
    const float* b1    = (const float*)d_in[14];
    const float* w2    = (const float*)d_in[15];
    const float* b2    = (const float*)d_in[16];

    float *h, *qkv, *y, *x1, *hid;
    float *wtqkv, *bqkv, *wto, *wt1, *wt2;
    cudaGetSymbolAddress((void**)&h,     g_h);
    cudaGetSymbolAddress((void**)&qkv,   g_qkv);
    cudaGetSymbolAddress((void**)&y,     g_y);
    cudaGetSymbolAddress((void**)&x1,    g_x1);
    cudaGetSymbolAddress((void**)&hid,   g_hid);
    cudaGetSymbolAddress((void**)&wtqkv, g_wtqkv);
    cudaGetSymbolAddress((void**)&bqkv,  g_bqkv);
    cudaGetSymbolAddress((void**)&wto,   g_wto);
    cudaGetSymbolAddress((void**)&wt1,   g_wt1);
    cudaGetSymbolAddress((void**)&wt2,   g_wt2);

    float* out = (float*)d_out;
    float* q = qkv;
    float* k = qkv + (size_t)M * C;
    float* v = qkv + (size_t)2 * M * C;

    cudaFuncSetAttribute(gemm_mma<0>, cudaFuncAttributeMaxDynamicSharedMemorySize, SMEM_SZ);
    cudaFuncSetAttribute(gemm_mma<1>, cudaFuncAttributeMaxDynamicSharedMemorySize, SMEM_SZ);
    cudaFuncSetAttribute(gemm_mma<2>, cudaFuncAttributeMaxDynamicSharedMemorySize, SMEM_SZ);
    cudaFuncSetAttribute(attn_mma,    cudaFuncAttributeMaxDynamicSharedMemorySize, SMEM_ATT);

    dim3 tb(32, 8);
    transpose_kernel<<<dim3(C/32,  C/32),  tb>>>(wq, wtqkv,             C,  C);
    transpose_kernel<<<dim3(C/32,  C/32),  tb>>>(wk, wtqkv + C * C,     C,  C);
    transpose_kernel<<<dim3(C/32,  C/32),  tb>>>(wv, wtqkv + 2 * C * C, C,  C);
    transpose_kernel<<<dim3(C/32,  C/32),  tb>>>(wo, wto, C,  C);
    transpose_kernel<<<dim3(FF/32, C/32),  tb>>>(w1, wt1, C,  FF);
    transpose_kernel<<<dim3(C/32,  FF/32), tb>>>(w2, wt2, FF, C);
    pack_bias<<<3, C>>>(bq, bk, bv, bqkv);

    ln_kernel<<<M, 256>>>(x, ln1_w, ln1_b, h);
    // fused QKV projection: N = 3072
    gemm_mma<0><<<dim3(3*C/128, M/128), 256, SMEM_SZ>>>(h, wtqkv, bqkv, nullptr, qkv, 3*C, C);
    attn_mma<<<dim3(T/64, Bb*Hh), 128, SMEM_ATT>>>(q, k, v, y);
    gemm_mma<1><<<dim3(C/128,  M/128), 256, SMEM_SZ>>>(y, wto, bo, x, x1, C, C);
    ln_kernel<<<M, 256>>>(x1, ln2_w, ln2_b, h);
    gemm_mma<2><<<dim3(FF/128, M/128), 256, SMEM_SZ>>>(h, wt1, b1, nullptr, hid, FF, C);
    gemm_mma<1><<<dim3(C/128,  M/128), 256, SMEM_SZ>>>(hid, wt2, b2, x1, out, C, FF);
}

// round 6
// speedup vs baseline: 6.6260x; 2.1049x over previous
#include <cuda_runtime.h>
#include <cuda_fp16.h>
#include <math.h>
#include <cstdint>

// Problem constants
constexpr int Bb = 2;
constexpr int T  = 2048;
constexpr int C  = 1024;
constexpr int Hh = 16;
constexpr int Dd = 64;
constexpr int M  = Bb * T;       // 4096 tokens
constexpr int FF = 4 * C;        // 4096

// ---------------- scratch (static device memory; no allocation) -------------
__device__ __half g_h  [M * C];             // LN output (fp16)
__device__ __half g_qkv[(size_t)3 * M * C]; // q|k|v, head layout [B,H,T,D]; q pre-scaled by 1/8
__device__ __half g_y  [M * C];             // attn out (fp16)
__device__ float  g_x1 [M * C];             // residual stream (fp32)
__device__ __half g_hid[(size_t)M * FF];    // MLP hidden (fp16)
// transposed weights, [N][K] layout, fp16
__device__ __half g_wtqkv[(size_t)3 * C * C];
__device__ float  g_bqkv [3 * C];
__device__ __half g_wto[C * C];
__device__ __half g_wt1[(size_t)C * FF];
__device__ __half g_wt2[(size_t)C * FF];

// ---------------- helpers ----------------------------------------------------
__device__ __forceinline__ uint32_t smem_u32(const void* p) {
    uint32_t a;
    asm("{ .reg .u64 t; cvta.to.shared.u64 t, %1; cvt.u32.u64 %0, t; }"
        : "=r"(a) : "l"(p));
    return a;
}
__device__ __forceinline__ void cp_async16(uint32_t dst, const void* src) {
    asm volatile("cp.async.cg.shared.global [%0], [%1], 16;"
                 :: "r"(dst), "l"(src) : "memory");
}
#define CP_COMMIT() asm volatile("cp.async.commit_group;" ::: "memory")
#define CP_WAIT(n)  asm volatile("cp.async.wait_group %0;" :: "n"(n) : "memory")

// fp16 MMA, fp32 accumulate: D(16x8) += A(16x16) * B(16x8)
__device__ __forceinline__ void mma_f16(float* c, const uint32_t* a, const uint32_t* b) {
    asm volatile(
        "mma.sync.aligned.m16n8k16.row.col.f32.f16.f16.f32 "
        "{%0,%1,%2,%3}, {%4,%5,%6,%7}, {%8,%9}, {%0,%1,%2,%3};"
        : "+f"(c[0]), "+f"(c[1]), "+f"(c[2]), "+f"(c[3])
        : "r"(a[0]), "r"(a[1]), "r"(a[2]), "r"(a[3]), "r"(b[0]), "r"(b[1]));
}
__device__ __forceinline__ void ldm_x4(uint32_t* r, uint32_t addr) {
    asm volatile("ldmatrix.sync.aligned.m8n8.x4.shared.b16 {%0,%1,%2,%3}, [%4];"
        : "=r"(r[0]), "=r"(r[1]), "=r"(r[2]), "=r"(r[3]) : "r"(addr));
}
__device__ __forceinline__ void ldm_x4_t(uint32_t* r, uint32_t addr) {
    asm volatile("ldmatrix.sync.aligned.m8n8.x4.trans.shared.b16 {%0,%1,%2,%3}, [%4];"
        : "=r"(r[0]), "=r"(r[1]), "=r"(r[2]), "=r"(r[3]) : "r"(addr));
}

// ---------------- fp16 mma.sync GEMM, 128x128x32, 3-stage, 2 CTA/SM ---------
// EPI: 0 = fused-QKV head-scatter to fp16 (+1/8 scale on Q), 1 = residual add fp32,
//      2 = exact GELU -> fp16
constexpr int LDKH = 40;                   // halfs per smem row (80 B, ldmatrix conflict-free)
constexpr int TILE_H = 128 * LDKH;         // halfs per tile
constexpr int NSTAGE = 3;
constexpr int SMEM_G = NSTAGE * 2 * TILE_H * 2;  // 61440 B

template<int EPI>
__global__ __launch_bounds__(256, 2)
void gemm_mma(const __half* __restrict__ A,     // [M,K] row-major fp16
              const __half* __restrict__ Bt,    // [N,K] row-major fp16
              const float* __restrict__ bias,   // [N]
              const float* __restrict__ resid,  // [M,N] (EPI==1)
              void* __restrict__ outv,
              int Nn, int Kk)
{
    extern __shared__ __half smh[];
    const uint32_t sb = smem_u32(smh);
    const int tid  = threadIdx.x;
    const int wid  = tid >> 5;
    const int lane = tid & 31;
    const int qr   = lane >> 2;
    const int qc   = lane & 3;
    const int bm = blockIdx.y * 128;
    const int bn = blockIdx.x * 128;
    const int warp_m = (wid & 1) * 64;
    const int warp_n = (wid >> 1) * 32;
    const int KT = Kk >> 5;

    const int lane15 = lane & 15;
    const int lanehi = lane >> 4;         // 0/1 -> +16B (8 halfs)
    const int bl8    = lane & 7;
    const int blg    = lane >> 3;         // 0..3 -> 16B chunk within 64B row

    auto issue = [&](int buf, int k0) {
        const uint32_t ao = sb + (uint32_t)(2 * buf * TILE_H) * 2;
        const uint32_t bo = ao + TILE_H * 2;
        #pragma unroll
        for (int i = 0; i < 2; i++) {
            int idx = i * 256 + tid;        // 512 chunks, 4 per row
            int r = idx >> 2, c = idx & 3;
            cp_async16(ao + r * 80 + c * 16, &A[(size_t)(bm + r) * Kk + k0 + c * 8]);
        }
        #pragma unroll
        for (int i = 0; i < 2; i++) {
            int idx = i * 256 + tid;
            int r = idx >> 2, c = idx & 3;
            cp_async16(bo + r * 80 + c * 16, &Bt[(size_t)(bn + r) * Kk + k0 + c * 8]);
        }
        CP_COMMIT();
    };

    float acc[4][4][4] = {};

    issue(0, 0);
    issue(1, 32);

    for (int kt = 0; kt < KT; kt++) {
        const int cur = kt % NSTAGE;
        CP_WAIT(1);
        __syncthreads();
        if (kt + 2 < KT) issue((kt + 2) % NSTAGE, (kt + 2) * 32);
        else             CP_COMMIT();

        const uint32_t ao = sb + (uint32_t)(2 * cur * TILE_H) * 2;
        const uint32_t bo = ao + TILE_H * 2;

        // B fragments: one ldm_x4 per jn covers full K=32 chunk (2 k16 frags)
        uint32_t bfr[4][4];
        #pragma unroll
        for (int jn = 0; jn < 4; jn++)
            ldm_x4(bfr[jn], bo + (uint32_t)(warp_n + jn * 8 + bl8) * 80 + blg * 16);

        #pragma unroll
        for (int ks = 0; ks < 2; ks++) {
            uint32_t a[4][4];
            #pragma unroll
            for (int im = 0; im < 4; im++)
                ldm_x4(a[im], ao + (uint32_t)(warp_m + im * 16 + lane15) * 80
                              + ks * 32 + lanehi * 16);
            #pragma unroll
            for (int im = 0; im < 4; im++)
                #pragma unroll
                for (int jn = 0; jn < 4; jn++)
                    mma_f16(acc[im][jn], a[im], &bfr[jn][ks * 2]);
        }
    }

    // epilogue
    #pragma unroll
    for (int im = 0; im < 4; im++) {
        const int r0 = bm + warp_m + im * 16 + qr;
        const int r1 = r0 + 8;
        #pragma unroll
        for (int jn = 0; jn < 4; jn++) {
            const int c0 = bn + warp_n + jn * 8 + qc * 2;
            const float2 bv = *(const float2*)&bias[c0];
            float2 v0, v1;
            v0.x = acc[im][jn][0] + bv.x;
            v0.y = acc[im][jn][1] + bv.y;
            v1.x = acc[im][jn][2] + bv.x;
            v1.y = acc[im][jn][3] + bv.y;
            if (EPI == 2) {
                v0.x = 0.5f * v0.x * (1.0f + erff(v0.x * 0.70710678118654752f));
                v0.y = 0.5f * v0.y * (1.0f + erff(v0.y * 0.70710678118654752f));
                v1.x = 0.5f * v1.x * (1.0f + erff(v1.x * 0.70710678118654752f));
                v1.y = 0.5f * v1.y * (1.0f + erff(v1.y * 0.70710678118654752f));
                __half* out = (__half*)outv;
                *(__half2*)&out[(size_t)r0 * Nn + c0] = __floats2half2_rn(v0.x, v0.y);
                *(__half2*)&out[(size_t)r1 * Nn + c0] = __floats2half2_rn(v1.x, v1.y);
            } else if (EPI == 1) {
                const float2 q0 = *(const float2*)&resid[(size_t)r0 * Nn + c0];
                const float2 q1 = *(const float2*)&resid[(size_t)r1 * Nn + c0];
                float* out = (float*)outv;
                v0.x += q0.x; v0.y += q0.y;
                v1.x += q1.x; v1.y += q1.y;
                *(float2*)&out[(size_t)r0 * Nn + c0] = v0;
                *(float2*)&out[(size_t)r1 * Nn + c0] = v1;
            } else {  // EPI == 0
                const int mat = c0 >> 10;          // 0=q 1=k 2=v
                if (mat == 0) {                    // pre-scale Q by 1/sqrt(D)=1/8
                    v0.x *= 0.125f; v0.y *= 0.125f;
                    v1.x *= 0.125f; v1.y *= 0.125f;
                }
                const int cc = c0 & 1023;
                const int hi = cc >> 6, dd = cc & 63;
                __half* ob = (__half*)outv + (size_t)mat * M * C;
                {
                    const int bi = r0 >> 11, t = r0 & 2047;
                    *(__half2*)&ob[(((size_t)(bi * Hh + hi)) * T + t) * Dd + dd] =
                        __floats2half2_rn(v0.x, v0.y);
                }
                {
                    const int bi = r1 >> 11, t = r1 & 2047;
                    *(__half2*)&ob[(((size_t)(bi * Hh + hi)) * T + t) * Dd + dd] =
                        __floats2half2_rn(v1.x, v1.y);
                }
            }
        }
    }
}

// ---------------- fp16 tensor-core flash attention (causal) ------------------
// 128 threads (4 warps), 64 q-rows/CTA; K/V cp.async double-buffered.
constexpr int LDAH = 72;                     // halfs per row (144 B)
constexpr int SQ_H  = 0;
constexpr int SK0_H = 64 * LDAH;
constexpr int SK1_H = 2 * 64 * LDAH;
constexpr int SV0_H = 3 * 64 * LDAH;
constexpr int SV1_H = 4 * 64 * LDAH;
constexpr int SP_H  = 5 * 64 * LDAH;
constexpr int SMEM_ATT = 6 * 64 * LDAH * 2;  // 55296 B

__global__ __launch_bounds__(128)
void attn_mma(const __half* __restrict__ Q,   // [B,H,T,D], pre-scaled by 1/8
              const __half* __restrict__ K,
              const __half* __restrict__ V,
              __half* __restrict__ Y)
{
    extern __shared__ __half smh[];
    const uint32_t sb = smem_u32(smh);
    const int tid  = threadIdx.x;
    const int wid  = tid >> 5;
    const int lane = tid & 31;
    const int qr   = lane >> 2;
    const int qc   = lane & 3;
    const int lane15 = lane & 15;
    const int lanehi = lane >> 4;
    const int bl8    = lane & 7;
    const int blg    = lane >> 3;

    const int bh = blockIdx.y;
    const int qb = (int)gridDim.x - 1 - (int)blockIdx.x;   // heavy CTAs first

    const __half* Qp = Q + (size_t)bh * T * Dd + (size_t)qb * 64 * Dd;
    const __half* Kp = K + (size_t)bh * T * Dd;
    const __half* Vp = V + (size_t)bh * T * Dd;

    // Q tile: plain copy (already scaled)
    #pragma unroll
    for (int i = 0; i < 4; i++) {
        int idx = i * 128 + tid;
        int r = idx >> 3, c = idx & 7;
        *(float4*)((char*)smh + r * 144 + c * 16) = *(const float4*)&Qp[r * 64 + c * 8];
    }

    auto issue_kv = [&](int buf, int kt) {
        const uint32_t kb = sb + (uint32_t)(SK0_H + buf * 64 * LDAH) * 2;
        const uint32_t vb = sb + (uint32_t)(SV0_H + buf * 64 * LDAH) * 2;
        const __half* Ks = Kp + (size_t)kt * 64 * 64;
        const __half* Vs = Vp + (size_t)kt * 64 * 64;
        #pragma unroll
        for (int i = 0; i < 4; i++) {
            int idx = i * 128 + tid;
            int r = idx >> 3, c = idx & 7;
            cp_async16(kb + r * 144 + c * 16, Ks + r * 64 + c * 8);
        }
        #pragma unroll
        for (int i = 0; i < 4; i++) {
            int idx = i * 128 + tid;
            int r = idx >> 3, c = idx & 7;
            cp_async16(vb + r * 144 + c * 16, Vs + r * 64 + c * 8);
        }
        CP_COMMIT();
    };

    issue_kv(0, 0);
    __syncthreads();   // Q visible

    // Q fragments, once: 4 k16 frags over D=64
    uint32_t qf[4][4];
    #pragma unroll
    for (int kc = 0; kc < 4; kc++)
        ldm_x4(qf[kc], sb + (uint32_t)(wid * 16 + lane15) * 144 + kc * 32 + lanehi * 16);

    float o[8][4] = {};
    float m0 = -1e30f, m1 = -1e30f, l0 = 0.0f, l1 = 0.0f;

    const uint32_t pwb = sb + (uint32_t)(SP_H + wid * 16 * LDAH) * 2;

    for (int kt = 0; kt <= qb; kt++) {
        const int cur = kt & 1;
        if (kt < qb) issue_kv(1 - cur, kt + 1);
        if (kt < qb) { CP_WAIT(1); } else { CP_WAIT(0); }
        __syncthreads();

        const uint32_t kb = sb + (uint32_t)(SK0_H + cur * 64 * LDAH) * 2;
        const uint32_t vb = sb + (uint32_t)(SV0_H + cur * 64 * LDAH) * 2;

        // ---- S = Q K^T (16x64 per warp) ----
        float sacc[8][4];
        #pragma unroll
        for (int jb = 0; jb < 8; jb++) {
            sacc[jb][0] = sacc[jb][1] = sacc[jb][2] = sacc[jb][3] = 0.0f;
            uint32_t r1[4], r2[4];
            ldm_x4(r1, kb + (uint32_t)(jb * 8 + bl8) * 144 + blg * 16);
            ldm_x4(r2, kb + (uint32_t)(jb * 8 + bl8) * 144 + blg * 16 + 64);
            mma_f16(sacc[jb], qf[0], &r1[0]);
            mma_f16(sacc[jb], qf[1], &r1[2]);
            mma_f16(sacc[jb], qf[2], &r2[0]);
            mma_f16(sacc[jb], qf[3], &r2[2]);
        }

        if (kt == qb) {   // causal mask on diagonal tile
            const int row0 = wid * 16 + qr;
            const int row1 = row0 + 8;
            #pragma unroll
            for (int jb = 0; jb < 8; jb++) {
                const int cb = jb * 8 + 2 * qc;
                if (cb     > row0) sacc[jb][0] = -1e30f;
                if (cb + 1 > row0) sacc[jb][1] = -1e30f;
                if (cb     > row1) sacc[jb][2] = -1e30f;
                if (cb + 1 > row1) sacc[jb][3] = -1e30f;
            }
        }

        // ---- online softmax ----
        float r0 = -1e30f, r1 = -1e30f;
        #pragma unroll
        for (int jb = 0; jb < 8; jb++) {
            r0 = fmaxf(r0, fmaxf(sacc[jb][0], sacc[jb][1]));
            r1 = fmaxf(r1, fmaxf(sacc[jb][2], sacc[jb][3]));
        }
        r0 = fmaxf(r0, __shfl_xor_sync(0xffffffffu, r0, 1));
        r0 = fmaxf(r0, __shfl_xor_sync(0xffffffffu, r0, 2));
        r1 = fmaxf(r1, __shfl_xor_sync(0xffffffffu, r1, 1));
        r1 = fmaxf(r1, __shfl_xor_sync(0xffffffffu, r1, 2));

        const float mn0 = fmaxf(m0, r0), mn1 = fmaxf(m1, r1);
        const float cr0 = __expf(m0 - mn0), cr1 = __expf(m1 - mn1);
        m0 = mn0; m1 = mn1;
        l0 *= cr0; l1 *= cr1;
        #pragma unroll
        for (int db = 0; db < 8; db++) {
            o[db][0] *= cr0; o[db][1] *= cr0;
            o[db][2] *= cr1; o[db][3] *= cr1;
        }

        #pragma unroll
        for (int jb = 0; jb < 8; jb++) {
            float p0 = __expf(sacc[jb][0] - m0);
            float p1 = __expf(sacc[jb][1] - m0);
            float p2 = __expf(sacc[jb][2] - m1);
            float p3 = __expf(sacc[jb][3] - m1);
            l0 += p0 + p1; l1 += p2 + p3;
            *(__half2*)((char*)smh + (pwb - sb) + qr * 144 + jb * 16 + 4 * qc) =
                __floats2half2_rn(p0, p1);
            *(__half2*)((char*)smh + (pwb - sb) + (qr + 8) * 144 + jb * 16 + 4 * qc) =
                __floats2half2_rn(p2, p3);
        }
        __syncwarp();

        // P fragments
        uint32_t pf[4][4];
        #pragma unroll
        for (int kc = 0; kc < 4; kc++)
            ldm_x4(pf[kc], pwb + (uint32_t)lane15 * 144 + kc * 32 + lanehi * 16);

        // ---- O += P V (B-frags via ldmatrix.trans on row-major V) ----
        #pragma unroll
        for (int dn = 0; dn < 8; dn++) {
            uint32_t v1[4], v2[4];
            ldm_x4_t(v1, vb + (uint32_t)lane * 144 + dn * 16);
            ldm_x4_t(v2, vb + (uint32_t)(32 + lane) * 144 + dn * 16);
            mma_f16(o[dn], pf[0], &v1[0]);
            mma_f16(o[dn], pf[1], &v1[2]);
            mma_f16(o[dn], pf[2], &v2[0]);
            mma_f16(o[dn], pf[3], &v2[2]);
        }
        __syncthreads();   // all warps done with cur before it is refilled
    }

    l0 += __shfl_xor_sync(0xffffffffu, l0, 1);
    l0 += __shfl_xor_sync(0xffffffffu, l0, 2);
    l1 += __shfl_xor_sync(0xffffffffu, l1, 1);
    l1 += __shfl_xor_sync(0xffffffffu, l1, 2);
    const float inv0 = 1.0f / l0, inv1 = 1.0f / l1;

    const int bi = bh >> 4, hi = bh & 15;
    const int q0 = qb * 64 + wid * 16 + qr;
    const int q1 = q0 + 8;
    __half* y0 = Y + ((size_t)(bi * T + q0)) * C + hi * Dd;
    __half* y1 = Y + ((size_t)(bi * T + q1)) * C + hi * Dd;
    #pragma unroll
    for (int dn = 0; dn < 8; dn++) {
        const int d = dn * 8 + 2 * qc;
        *(__half2*)&y0[d] = __floats2half2_rn(o[dn][0] * inv0, o[dn][1] * inv0);
        *(__half2*)&y1[d] = __floats2half2_rn(o[dn][2] * inv1, o[dn][3] * inv1);
    }
}

// ---------------- weight transposes -> fp16 [N][K] ---------------------------
__global__ void transpose_qkvo(const float* __restrict__ wq, const float* __restrict__ wk,
                               const float* __restrict__ wv, const float* __restrict__ wo,
                               __half* __restrict__ oq, __half* __restrict__ ok,
                               __half* __restrict__ ov, __half* __restrict__ oo)
{
    __shared__ float tile[32][33];
    const int z = blockIdx.z;
    const float* in = (z == 0) ? wq : (z == 1) ? wk : (z == 2) ? wv : wo;
    __half* out = (z == 0) ? oq : (z == 1) ? ok : (z == 2) ? ov : oo;
    int x = blockIdx.x * 32 + threadIdx.x;
    int y = blockIdx.y * 32 + threadIdx.y;
    #pragma unroll
    for (int j = 0; j < 32; j += 8)
        tile[threadIdx.y + j][threadIdx.x] = in[(size_t)(y + j) * C + x];
    __syncthreads();
    int xo = blockIdx.y * 32 + threadIdx.x;
    int yo = blockIdx.x * 32 + threadIdx.y;
    #pragma unroll
    for (int j = 0; j < 32; j += 8)
        out[(size_t)(yo + j) * C + xo] = __float2half_rn(tile[threadIdx.x][threadIdx.y + j]);
}

__global__ void transpose_h(const float* __restrict__ in, __half* __restrict__ out,
                            int R, int Cc)
{
    __shared__ float tile[32][33];
    int x = blockIdx.x * 32 + threadIdx.x;
    int y = blockIdx.y * 32 + threadIdx.y;
    #pragma unroll
    for (int j = 0; j < 32; j += 8)
        tile[threadIdx.y + j][threadIdx.x] = in[(size_t)(y + j) * Cc + x];
    __syncthreads();
    int xo = blockIdx.y * 32 + threadIdx.x;
    int yo = blockIdx.x * 32 + threadIdx.y;
    #pragma unroll
    for (int j = 0; j < 32; j += 8)
        out[(size_t)(yo + j) * R + xo] = __float2half_rn(tile[threadIdx.x][threadIdx.y + j]);
}

__global__ void pack_bias(const float* __restrict__ a, const float* __restrict__ b,
                          const float* __restrict__ c, float* __restrict__ out)
{
    int i = threadIdx.x;
    const float* src = (blockIdx.x == 0) ? a : (blockIdx.x == 1) ? b : c;
    out[blockIdx.x * C + i] = src[i];
}

// ---------------- LayerNorm (fp32 in -> fp16 out) ----------------------------
__global__ void ln_kernel(const float* __restrict__ X,
                          const float* __restrict__ w,
                          const float* __restrict__ b,
                          __half* __restrict__ out)
{
    int row = blockIdx.x;
    int tid = threadIdx.x;
    const float4 xv = *(const float4*)&X[(size_t)row * C + tid * 4];

    float s  = xv.x + xv.y + xv.z + xv.w;
    float sq = xv.x*xv.x + xv.y*xv.y + xv.z*xv.z + xv.w*xv.w;
    #pragma unroll
    for (int off = 16; off > 0; off >>= 1) {
        s  += __shfl_xor_sync(0xffffffffu, s,  off);
        sq += __shfl_xor_sync(0xffffffffu, sq, off);
    }
    __shared__ float ss[8], ssq[8];
    __shared__ float mu_s, rstd_s;
    int lane = tid & 31, wid = tid >> 5;
    if (lane == 0) { ss[wid] = s; ssq[wid] = sq; }
    __syncthreads();
    if (tid == 0) {
        float ts = 0.f, tq = 0.f;
        #pragma unroll
        for (int i = 0; i < 8; i++) { ts += ss[i]; tq += ssq[i]; }
        float mu  = ts * (1.0f / C);
        float var = tq * (1.0f / C) - mu * mu;
        mu_s = mu; rstd_s = rsqrtf(var + 1e-5f);
    }
    __syncthreads();
    float mu = mu_s, r = rstd_s;
    const float4 wv = *(const float4*)&w[tid * 4];
    const float4 bv = *(const float4*)&b[tid * 4];
    __half2 h0 = __floats2half2_rn((xv.x - mu) * r * wv.x + bv.x,
                                   (xv.y - mu) * r * wv.y + bv.y);
    __half2 h1 = __floats2half2_rn((xv.z - mu) * r * wv.z + bv.z,
                                   (xv.w - mu) * r * wv.w + bv.w);
    *(__half2*)&out[(size_t)row * C + tid * 4]     = h0;
    *(__half2*)&out[(size_t)row * C + tid * 4 + 2] = h1;
}

// ---------------- launcher ----------------------------------------------------
extern "C" void kernel_launch(void* const* d_in, const int* in_sizes, int n_in,
                              void* d_out, int out_size)
{
    const float* x     = (const float*)d_in[0];
    const float* ln1_w = (const float*)d_in[1];
    const float* ln1_b = (const float*)d_in[2];
    const float* wq    = (const float*)d_in[3];
    const float* bq    = (const float*)d_in[4];
    const float* wk    = (const float*)d_in[5];
    const float* bk    = (const float*)d_in[6];
    const float* wv    = (const float*)d_in[7];
    const float* bv    = (const float*)d_in[8];
    const float* wo    = (const float*)d_in[9];
    const float* bo    = (const float*)d_in[10];
    const float* ln2_w = (const float*)d_in[11];
    const float* ln2_b = (const float*)d_in[12];
    const float* w1    = (const float*)d_in[13];
    const float* b1    = (const float*)d_in[14];
    const float* w2    = (const float*)d_in[15];
    const float* b2    = (const float*)d_in[16];

    __half *h, *qkv, *y, *hid, *wtqkv, *wto, *wt1, *wt2;
    float *x1, *bqkv;
    cudaGetSymbolAddress((void**)&h,     g_h);
    cudaGetSymbolAddress((void**)&qkv,   g_qkv);
    cudaGetSymbolAddress((void**)&y,     g_y);
    cudaGetSymbolAddress((void**)&x1,    g_x1);
    cudaGetSymbolAddress((void**)&hid,   g_hid);
    cudaGetSymbolAddress((void**)&wtqkv, g_wtqkv);
    cudaGetSymbolAddress((void**)&bqkv,  g_bqkv);
    cudaGetSymbolAddress((void**)&wto,   g_wto);
    cudaGetSymbolAddress((void**)&wt1,   g_wt1);
    cudaGetSymbolAddress((void**)&wt2,   g_wt2);

    float* out = (float*)d_out;
    __half* q = qkv;
    __half* k = qkv + (size_t)M * C;
    __half* v = qkv + (size_t)2 * M * C;

    cudaFuncSetAttribute(gemm_mma<0>, cudaFuncAttributeMaxDynamicSharedMemorySize, SMEM_G);
    cudaFuncSetAttribute(gemm_mma<1>, cudaFuncAttributeMaxDynamicSharedMemorySize, SMEM_G);
    cudaFuncSetAttribute(gemm_mma<2>, cudaFuncAttributeMaxDynamicSharedMemorySize, SMEM_G);
    cudaFuncSetAttribute(attn_mma,    cudaFuncAttributeMaxDynamicSharedMemorySize, SMEM_ATT);

    dim3 tb(32, 8);
    transpose_qkvo<<<dim3(C/32, C/32, 4), tb>>>(wq, wk, wv, wo,
                                                wtqkv, wtqkv + C * C, wtqkv + 2 * C * C, wto);
    transpose_h<<<dim3(FF/32, C/32),  tb>>>(w1, wt1, C,  FF);
    transpose_h<<<dim3(C/32,  FF/32), tb>>>(w2, wt2, FF, C);
    pack_bias<<<3, C>>>(bq, bk, bv, bqkv);

    ln_kernel<<<M, 256>>>(x, ln1_w, ln1_b, h);
    gemm_mma<0><<<dim3(3*C/128, M/128), 256, SMEM_G>>>(h, wtqkv, bqkv, nullptr, qkv, 3*C, C);
    attn_mma<<<dim3(T/64, Bb*Hh), 128, SMEM_ATT>>>(q, k, v, y);
    gemm_mma<1><<<dim3(C/128,  M/128), 256, SMEM_G>>>(y, wto, bo, x, x1, C, C);
    ln_kernel<<<M, 256>>>(x1, ln2_w, ln2_b, h);
    gemm_mma<2><<<dim3(FF/128, M/128), 256, SMEM_G>>>(h, wt1, b1, nullptr, hid, FF, C);
    gemm_mma<1><<<dim3(C/128,  M/128), 256, SMEM_G>>>(hid, wt2, b2, x1, out, C, FF);
}